// round 1
// baseline (speedup 1.0000x reference)
#include <cuda_runtime.h>
#include <cuda_bf16.h>

typedef unsigned long long ull;

#define Nn 4096
#define IND 512
#define OD 512
#define Hh 8
#define Dd 64
#define ALPHA 0.2f
#define EPSV 1e-5f

#define BI 32
#define BJ 16
#define CBLOCKS (Nn / BI)   // 128

// ---------------- scratch (no allocations allowed) ----------------
__device__ float g_Wh[Nn * OD];                 // x @ W^T
__device__ float g_hp[Nn * OD];                 // h_prime before layernorm
__device__ float g_sd[Hh * Nn], g_ss[Hh * Nn];  // dst/src scores per (head, node)
__device__ float g_E1d[Hh * Nn], g_E2d[Hh * Nn];
__device__ float g_E1s[Hh * Nn], g_E2s[Hh * Nn];
__device__ float g_cs[CBLOCKS * OD], g_cq[CBLOCKS * OD];  // per-block column partial sums
__device__ float g_mean[OD], g_rstd[OD];

// ---------------- packed f32x2 helpers ----------------
__device__ __forceinline__ ull pack2(float p) {
    unsigned b = __float_as_uint(p);
    ull r;
    asm("mov.b64 %0, {%1, %1};" : "=l"(r) : "r"(b));
    return r;
}
#define FFMA2(d, a, b) asm("fma.rn.f32x2 %0, %1, %2, %0;" : "+l"(d) : "l"(a), "l"(b))

// ================= Kernel A: Wh = x @ W^T =================
// M=4096, N=512, K=512. 64x64 tile, BK=16, 256 threads, 4x4 microtile.
__global__ void __launch_bounds__(256) gemm_xWt_kernel(const float* __restrict__ x,
                                                       const float* __restrict__ W) {
    __shared__ float As[16][64];
    __shared__ float Bs[16][64];
    const int i0 = blockIdx.y * 64;
    const int o0 = blockIdx.x * 64;
    const int t = threadIdx.x;
    const int tx = t & 15, ty = t >> 4;
    const int lrow = t >> 2, lkq = t & 3;

    float acc[4][4];
#pragma unroll
    for (int r = 0; r < 4; r++)
#pragma unroll
        for (int c = 0; c < 4; c++) acc[r][c] = 0.f;

    for (int k0 = 0; k0 < IND; k0 += 16) {
        float4 va = *(const float4*)&x[(i0 + lrow) * IND + k0 + lkq * 4];
        float4 vb = *(const float4*)&W[(o0 + lrow) * IND + k0 + lkq * 4];
        As[lkq * 4 + 0][lrow] = va.x; As[lkq * 4 + 1][lrow] = va.y;
        As[lkq * 4 + 2][lrow] = va.z; As[lkq * 4 + 3][lrow] = va.w;
        Bs[lkq * 4 + 0][lrow] = vb.x; Bs[lkq * 4 + 1][lrow] = vb.y;
        Bs[lkq * 4 + 2][lrow] = vb.z; Bs[lkq * 4 + 3][lrow] = vb.w;
        __syncthreads();
#pragma unroll
        for (int kk = 0; kk < 16; kk++) {
            float4 ar = *(const float4*)&As[kk][ty * 4];
            float4 br = *(const float4*)&Bs[kk][tx * 4];
            float a4[4] = {ar.x, ar.y, ar.z, ar.w};
            float b4[4] = {br.x, br.y, br.z, br.w};
#pragma unroll
            for (int r = 0; r < 4; r++)
#pragma unroll
                for (int c = 0; c < 4; c++) acc[r][c] += a4[r] * b4[c];
        }
        __syncthreads();
    }
#pragma unroll
    for (int r = 0; r < 4; r++) {
        float4 o = make_float4(acc[r][0], acc[r][1], acc[r][2], acc[r][3]);
        *(float4*)&g_Wh[(i0 + ty * 4 + r) * OD + o0 + tx * 4] = o;
    }
}

// ================= Kernel B: per-(node, head) scores + exp tables =================
__global__ void __launch_bounds__(256) scores_kernel(const float* __restrict__ a) {
    const int t = blockIdx.x * 256 + threadIdx.x;  // 0..32767
    const int j = t >> 3, h = t & 7;
    const float* wrow = &g_Wh[j * OD + h * Dd];
    float ssrc = 0.f, sdst = 0.f;
#pragma unroll
    for (int d = 0; d < Dd; d += 4) {
        float4 wv = *(const float4*)&wrow[d];
        float4 as = *(const float4*)&a[d];
        float4 ad = *(const float4*)&a[Dd + d];
        ssrc += wv.x * as.x + wv.y * as.y + wv.z * as.z + wv.w * as.w;
        sdst += wv.x * ad.x + wv.y * ad.y + wv.z * ad.z + wv.w * ad.w;
    }
    const int idx = h * Nn + j;
    g_ss[idx] = ssrc;
    g_sd[idx] = sdst;
    g_E1s[idx] = expf(ssrc);
    g_E2s[idx] = expf(ALPHA * ssrc);
    g_E1d[idx] = expf(sdst);
    g_E2d[idx] = expf(ALPHA * sdst);
}

// ================= Kernel C: attention aggregation =================
// Block: BI=32 rows (i), all 512 output cols. Loop j in tiles of BJ=16.
// Thread GEMM tile: 8 rows x 8 cols (one head per thread's 8 cols).
__global__ void __launch_bounds__(256, 1) attn_kernel(const int* __restrict__ adj) {
    extern __shared__ float smem[];
    float* WhS  = smem;            // 16*512 = 8192
    float* PS   = WhS + 8192;      // 16*8*32 = 4096
    float* ssS  = PS + 4096;       // 8*16
    float* E1sS = ssS + 128;       // 8*16
    float* E2sS = E1sS + 128;      // 8*16
    float* zS   = E2sS + 128;      // 8*32
    int*   adjS = (int*)(zS + 256);  // 16*32 ints, layout [jj][ii]

    const int i0 = blockIdx.x * BI;
    const int t = threadIdx.x;

    // P-phase identity: fixed (head, row) for this thread across the whole j loop
    const int ph = (t >> 5) & 7;
    const int pii = t & 31;
    const float sdv = g_sd[ph * Nn + i0 + pii];
    const float e1d = g_E1d[ph * Nn + i0 + pii];
    const float e2d = g_E2d[ph * Nn + i0 + pii];
    float zacc = 0.f;

    // GEMM-phase identity
    const int r = t >> 6;        // 0..3  (rows r*8 .. r*8+7)
    const int c = t & 63;        // 0..63 (cols c*8 .. c*8+7)
    const int head = c >> 3;

    ull acc[8][4];
#pragma unroll
    for (int i8 = 0; i8 < 8; i8++)
#pragma unroll
        for (int c2 = 0; c2 < 4; c2++) acc[i8][c2] = 0ull;

    const int lii = t >> 3, ljq = t & 7;  // adj loader

    for (int j0 = 0; j0 < Nn; j0 += BJ) {
        __syncthreads();
        // ---- stage Wh tile [BJ][512] ----
#pragma unroll
        for (int q = 0; q < 8; q++) {
            int idx = t + q * 256;         // float4 index 0..2047
            int jj = idx >> 7, c4 = idx & 127;
            *(float4*)&WhS[jj * OD + c4 * 4] =
                *(const float4*)&g_Wh[(j0 + jj) * OD + c4 * 4];
        }
        // ---- stage adj tile (transposed [jj][ii]) ----
        {
            int2 av = *(const int2*)&adj[(i0 + lii) * Nn + j0 + ljq * 2];
            adjS[(ljq * 2) * BI + lii] = av.x;
            adjS[(ljq * 2 + 1) * BI + lii] = av.y;
        }
        // ---- stage per-j scalars ----
        if (t < 128) {
            int h = t >> 4, jj = t & 15;
            ssS[h * 16 + jj]  = g_ss[h * Nn + j0 + jj];
            E1sS[h * 16 + jj] = g_E1s[h * Nn + j0 + jj];
            E2sS[h * 16 + jj] = g_E2s[h * Nn + j0 + jj];
        }
        __syncthreads();

        // ---- P phase: probabilities for this tile + running Z ----
#pragma unroll
        for (int jj = 0; jj < BJ; jj++) {
            int m = adjS[jj * BI + pii];
            float p = 0.f;
            if (m > 0) {
                float tt = sdv + ssS[ph * 16 + jj];
                p = (tt >= 0.f) ? (e1d * E1sS[ph * 16 + jj])
                                : (e2d * E2sS[ph * 16 + jj]);
            }
            zacc += p;
            PS[(jj * Hh + ph) * BI + pii] = p;
        }
        __syncthreads();

        // ---- GEMM phase: acc += P * Wh ----
#pragma unroll 4
        for (int jj = 0; jj < BJ; jj++) {
            const ulonglong2 w0 = *(const ulonglong2*)&WhS[jj * OD + c * 8];
            const ulonglong2 w1 = *(const ulonglong2*)&WhS[jj * OD + c * 8 + 4];
            const float4 pa = *(const float4*)&PS[(jj * Hh + head) * BI + r * 8];
            const float4 pb = *(const float4*)&PS[(jj * Hh + head) * BI + r * 8 + 4];
#define ROWF(i8, pv)                                   \
            {                                          \
                ull pp_ = pack2(pv);                   \
                FFMA2(acc[i8][0], pp_, w0.x);          \
                FFMA2(acc[i8][1], pp_, w0.y);          \
                FFMA2(acc[i8][2], pp_, w1.x);          \
                FFMA2(acc[i8][3], pp_, w1.y);          \
            }
            ROWF(0, pa.x) ROWF(1, pa.y) ROWF(2, pa.z) ROWF(3, pa.w)
            ROWF(4, pb.x) ROWF(5, pb.y) ROWF(6, pb.z) ROWF(7, pb.w)
#undef ROWF
        }
    }

    // ---- softmax denominators ----
    __syncthreads();
    zS[ph * BI + pii] = zacc;
    __syncthreads();

    // ---- epilogue: normalize, write h_prime, accumulate column partials ----
    float cs[8], cq[8];
#pragma unroll
    for (int k = 0; k < 8; k++) { cs[k] = 0.f; cq[k] = 0.f; }

#pragma unroll
    for (int i8 = 0; i8 < 8; i8++) {
        int row = r * 8 + i8;
        float inv = 1.0f / zS[head * BI + row];
        float v[8];
#pragma unroll
        for (int c2 = 0; c2 < 4; c2++) {
            ull a = acc[i8][c2];
            v[2 * c2]     = __uint_as_float((unsigned)a) * inv;
            v[2 * c2 + 1] = __uint_as_float((unsigned)(a >> 32)) * inv;
        }
        float4 o0 = make_float4(v[0], v[1], v[2], v[3]);
        float4 o1 = make_float4(v[4], v[5], v[6], v[7]);
        *(float4*)&g_hp[(i0 + row) * OD + c * 8] = o0;
        *(float4*)&g_hp[(i0 + row) * OD + c * 8 + 4] = o1;
#pragma unroll
        for (int k = 0; k < 8; k++) { cs[k] += v[k]; cq[k] += v[k] * v[k]; }
    }

    // deterministic per-block column reduction through PS (reused as [4][512] x2)
    __syncthreads();
#pragma unroll
    for (int k = 0; k < 8; k++) {
        PS[r * OD + c * 8 + k] = cs[k];
        PS[2048 + r * OD + c * 8 + k] = cq[k];
    }
    __syncthreads();
    for (int col = t; col < OD; col += 256) {
        float s = PS[col] + PS[OD + col] + PS[2 * OD + col] + PS[3 * OD + col];
        float q = PS[2048 + col] + PS[2048 + OD + col] + PS[2048 + 2 * OD + col] +
                  PS[2048 + 3 * OD + col];
        g_cs[blockIdx.x * OD + col] = s;
        g_cq[blockIdx.x * OD + col] = q;
    }
}

// ================= Kernel D: column mean / rstd =================
__global__ void __launch_bounds__(512) colstats_kernel() {
    const int col = threadIdx.x;
    float s = 0.f, q = 0.f;
    for (int b = 0; b < CBLOCKS; b++) {
        s += g_cs[b * OD + col];
        q += g_cq[b * OD + col];
    }
    float mean = s * (1.0f / Nn);
    float var = q * (1.0f / Nn) - mean * mean;
    g_mean[col] = mean;
    g_rstd[col] = rsqrtf(var + EPSV);
}

// ================= Kernel E: layernorm(gamma,beta) + relu =================
__global__ void __launch_bounds__(256) norm_relu_kernel(const float* __restrict__ gamma,
                                                        const float* __restrict__ beta,
                                                        float* __restrict__ out) {
    const int idx4 = blockIdx.x * 256 + threadIdx.x;  // 0..524287
    const int base = idx4 * 4;
    const int col = base & (OD - 1);
    float4 xv = *(const float4*)&g_hp[base];
    float4 mn = *(const float4*)&g_mean[col];
    float4 rs = *(const float4*)&g_rstd[col];
    float4 ga = *(const float4*)&gamma[col];
    float4 be = *(const float4*)&beta[col];
    float4 o;
    o.x = fmaxf(0.f, ga.x * (xv.x - mn.x) * rs.x + be.x);
    o.y = fmaxf(0.f, ga.y * (xv.y - mn.y) * rs.y + be.y);
    o.z = fmaxf(0.f, ga.z * (xv.z - mn.z) * rs.z + be.z);
    o.w = fmaxf(0.f, ga.w * (xv.w - mn.w) * rs.w + be.w);
    *(float4*)&out[base] = o;
}

// ================= launch =================
extern "C" void kernel_launch(void* const* d_in, const int* in_sizes, int n_in,
                              void* d_out, int out_size) {
    const float* x     = (const float*)d_in[0];
    const int*   adj   = (const int*)d_in[1];
    const float* W     = (const float*)d_in[2];
    const float* a     = (const float*)d_in[3];
    const float* gamma = (const float*)d_in[4];
    const float* beta  = (const float*)d_in[5];
    float* out = (float*)d_out;

    const int smemC = 53760;
    cudaFuncSetAttribute(attn_kernel, cudaFuncAttributeMaxDynamicSharedMemorySize, smemC);

    gemm_xWt_kernel<<<dim3(OD / 64, Nn / 64), 256>>>(x, W);
    scores_kernel<<<(Nn * Hh) / 256, 256>>>(a);
    attn_kernel<<<CBLOCKS, 256, smemC>>>(adj);
    colstats_kernel<<<1, 512>>>();
    norm_relu_kernel<<<(Nn * OD / 4) / 256, 256>>>(gamma, beta, out);
}

// round 5
// speedup vs baseline: 3.5818x; 3.5818x over previous
#include <cuda_runtime.h>
#include <cuda_bf16.h>
#include <cstdint>

#define Nn 4096
#define IND 512
#define OD 512
#define Hh 8
#define Dd 64
#define ALPHA 0.2f
#define EPSV 1e-5f
#define LOG2E 1.4426950408889634f
#define ITILES 32
#define NTILES 32

__device__ float g_Wh[Nn * OD];
__device__ __nv_bfloat16 g_Bhi[Nn * OD];   // bf16(Wh) hi, [i][o]
__device__ __nv_bfloat16 g_Blo[Nn * OD];   // residual lo, [i][o]
__device__ float g_sdL[Hh * Nn], g_ssL[Hh * Nn];   // scores * log2(e)
__device__ unsigned g_mask[Nn * (Nn / 32)];
__device__ float g_hp[Nn * OD];
__device__ float g_cs[ITILES * OD], g_cq[ITILES * OD];
__device__ float g_mean[OD], g_rstd[OD];

__device__ __forceinline__ unsigned bfpack(float hi, float lo) {
    unsigned r;
    asm("cvt.rn.bf16x2.f32 %0, %1, %2;" : "=r"(r) : "f"(hi), "f"(lo));
    return r;
}
__device__ __forceinline__ float lowf(unsigned u) { return __uint_as_float(u << 16); }
__device__ __forceinline__ float hif(unsigned u) { return __uint_as_float(u & 0xffff0000u); }
__device__ __forceinline__ float ex2f(float x) {
    float r;
    asm("ex2.approx.ftz.f32 %0, %1;" : "=f"(r) : "f"(x));
    return r;
}
__device__ __forceinline__ uint32_t smem_u32(const void* p) {
    uint32_t a;
    asm("{ .reg .u64 t; cvta.to.shared.u64 t, %1; cvt.u32.u64 %0, t; }" : "=r"(a) : "l"(p));
    return a;
}
__device__ __forceinline__ float pfun(float tL, unsigned bit) {
    float g = fmaxf(tL, ALPHA * tL);
    float p = ex2f(g);
    return bit ? p : 0.f;
}

#define MMA(cc, A0, A1, A2, A3, B0, B1)                                            \
    asm volatile("mma.sync.aligned.m16n8k16.row.col.f32.bf16.bf16.f32 "            \
                 "{%0,%1,%2,%3},{%4,%5,%6,%7},{%8,%9},{%0,%1,%2,%3};"              \
                 : "+f"(cc[0]), "+f"(cc[1]), "+f"(cc[2]), "+f"(cc[3])              \
                 : "r"(A0), "r"(A1), "r"(A2), "r"(A3), "r"(B0), "r"(B1))

#define LDMX2T(r0, r1, addr)                                                       \
    asm volatile("ldmatrix.sync.aligned.m8n8.x2.trans.shared.b16 {%0,%1},[%2];"    \
                 : "=r"(r0), "=r"(r1) : "r"(addr))

// ================= Kernel A: Wh = x @ W^T + bf16 hi/lo emit =================
__global__ void __launch_bounds__(256) gemm_xWt_kernel(const float* __restrict__ x,
                                                       const float* __restrict__ W) {
    __shared__ float As[16][64];
    __shared__ float Bs[16][64];
    const int i0 = blockIdx.y * 64, o0 = blockIdx.x * 64;
    const int t = threadIdx.x;
    const int tx = t & 15, ty = t >> 4;
    const int lrow = t >> 2, lkq = t & 3;
    float acc[4][4];
#pragma unroll
    for (int r = 0; r < 4; r++)
#pragma unroll
        for (int c = 0; c < 4; c++) acc[r][c] = 0.f;
    for (int k0 = 0; k0 < IND; k0 += 16) {
        float4 va = *(const float4*)&x[(i0 + lrow) * IND + k0 + lkq * 4];
        float4 vb = *(const float4*)&W[(o0 + lrow) * IND + k0 + lkq * 4];
        As[lkq * 4 + 0][lrow] = va.x; As[lkq * 4 + 1][lrow] = va.y;
        As[lkq * 4 + 2][lrow] = va.z; As[lkq * 4 + 3][lrow] = va.w;
        Bs[lkq * 4 + 0][lrow] = vb.x; Bs[lkq * 4 + 1][lrow] = vb.y;
        Bs[lkq * 4 + 2][lrow] = vb.z; Bs[lkq * 4 + 3][lrow] = vb.w;
        __syncthreads();
#pragma unroll
        for (int kk = 0; kk < 16; kk++) {
            float4 ar = *(const float4*)&As[kk][ty * 4];
            float4 br = *(const float4*)&Bs[kk][tx * 4];
            float a4[4] = {ar.x, ar.y, ar.z, ar.w};
            float b4[4] = {br.x, br.y, br.z, br.w};
#pragma unroll
            for (int r = 0; r < 4; r++)
#pragma unroll
                for (int c = 0; c < 4; c++) acc[r][c] += a4[r] * b4[c];
        }
        __syncthreads();
    }
#pragma unroll
    for (int r = 0; r < 4; r++) {
        const int i = i0 + ty * 4 + r;
        *(float4*)&g_Wh[(size_t)i * OD + o0 + tx * 4] =
            make_float4(acc[r][0], acc[r][1], acc[r][2], acc[r][3]);
        unsigned h01 = bfpack(acc[r][1], acc[r][0]);
        unsigned h23 = bfpack(acc[r][3], acc[r][2]);
        unsigned l01 = bfpack(acc[r][1] - hif(h01), acc[r][0] - lowf(h01));
        unsigned l23 = bfpack(acc[r][3] - hif(h23), acc[r][2] - lowf(h23));
        *(uint2*)&g_Bhi[(size_t)i * OD + o0 + tx * 4] = make_uint2(h01, h23);
        *(uint2*)&g_Blo[(size_t)i * OD + o0 + tx * 4] = make_uint2(l01, l23);
    }
}

// ================= Kernel B: adj -> bitmask =================
__global__ void __launch_bounds__(256) maskpack_kernel(const int* __restrict__ adj) {
    const int row = blockIdx.x;
    const int w = threadIdx.x >> 5, lane = threadIdx.x & 31;
    const int* arow = adj + (size_t)row * Nn;
#pragma unroll
    for (int k = 0; k < 16; k++) {
        int word = w * 16 + k;
        unsigned bal = __ballot_sync(0xffffffffu, arow[word * 32 + lane] > 0);
        if (lane == 0) g_mask[row * 128 + word] = bal;
    }
}

// ================= Kernel C: scores (prescaled by log2 e) =================
__global__ void __launch_bounds__(256) scores_kernel(const float* __restrict__ a) {
    const int t = blockIdx.x * 256 + threadIdx.x;
    const int j = t >> 3, h = t & 7;
    const float* wrow = &g_Wh[(size_t)j * OD + h * Dd];
    float ssrc = 0.f, sdst = 0.f;
#pragma unroll
    for (int d = 0; d < Dd; d += 4) {
        float4 wv = *(const float4*)&wrow[d];
        float4 as = *(const float4*)&a[d];
        float4 ad = *(const float4*)&a[Dd + d];
        ssrc += wv.x * as.x + wv.y * as.y + wv.z * as.z + wv.w * as.w;
        sdst += wv.x * ad.x + wv.y * ad.y + wv.z * ad.z + wv.w * ad.w;
    }
    g_ssL[h * Nn + j] = ssrc * LOG2E;
    g_sdL[h * Nn + j] = sdst * LOG2E;
}

// ================= Kernel D: HMMA attention aggregation =================
__global__ void __launch_bounds__(256, 2) attn_mma_kernel() {
    __shared__ __align__(16) unsigned char sBhi[16384];
    __shared__ __align__(16) unsigned char sBlo[16384];
    __shared__ float ssLS[128];
    __shared__ unsigned maskS[512];
    __shared__ float colS[8 * 64], colQ[8 * 64];

    const int h = blockIdx.x, it = blockIdx.y, i0 = it * 128;
    const int t = threadIdx.x, w = t >> 5, lane = t & 31;
    const int l3 = lane & 3, l7 = lane & 7, l15 = lane & 15;
    const int rA0 = w * 16 + (lane >> 2), rA1 = rA0 + 8;
    const float sd0 = g_sdL[h * Nn + i0 + rA0];
    const float sd1 = g_sdL[h * Nn + i0 + rA1];
    const uint32_t bhiB = smem_u32(sBhi), bloB = smem_u32(sBlo);

    float z0 = 0.f, z1 = 0.f;
    float c[8][4];
#pragma unroll
    for (int nt = 0; nt < 8; nt++)
#pragma unroll
        for (int q = 0; q < 4; q++) c[nt][q] = 0.f;

    for (int tl = 0; tl < NTILES; tl++) {
        const int j0 = tl * 128;
        uint4 bv[8];
#pragma unroll
        for (int q = 0; q < 8; q++) {
            int idx = t + q * 256;
            int isLo = idx >> 10, id = idx & 1023;
            int j = id >> 3, cc = id & 7;
            const __nv_bfloat16* src = isLo ? g_Blo : g_Bhi;
            bv[q] = *(const uint4*)&src[(size_t)(j0 + j) * OD + h * 64 + cc * 8];
        }
        float ssld = (t < 128) ? g_ssL[h * Nn + j0 + t] : 0.f;
        unsigned m0 = g_mask[(size_t)(i0 + (t >> 2)) * 128 + (j0 >> 5) + (t & 3)];
        unsigned m1 = g_mask[(size_t)(i0 + 64 + (t >> 2)) * 128 + (j0 >> 5) + (t & 3)];
        __syncthreads();
#pragma unroll
        for (int q = 0; q < 8; q++) {
            int idx = t + q * 256;
            int isLo = idx >> 10, id = idx & 1023;
            int j = id >> 3, cc = id & 7;
            unsigned off = (unsigned)j * 128u + (unsigned)((cc ^ (j & 7)) * 16);
            *(uint4*)((isLo ? sBlo : sBhi) + off) = bv[q];
        }
        if (t < 128) ssLS[t] = ssld;
        maskS[t] = m0;
        maskS[t + 256] = m1;
        __syncthreads();

#pragma unroll
        for (int kk = 0; kk < 8; kk++) {
            const int jc = kk * 16 + l3 * 2;
            const float ss0 = ssLS[jc], ss1 = ssLS[jc + 1];
            const float ss8 = ssLS[jc + 8], ss9 = ssLS[jc + 9];
            const unsigned sh = (kk & 1) * 16 + l3 * 2;
            const unsigned mw0 = maskS[rA0 * 4 + (kk >> 1)] >> sh;
            const unsigned mw1 = maskS[rA1 * 4 + (kk >> 1)] >> sh;

            float p00 = pfun(sd0 + ss0, mw0 & 1u);
            float p01 = pfun(sd0 + ss1, mw0 & 2u);
            float p08 = pfun(sd0 + ss8, (mw0 >> 8) & 1u);
            float p09 = pfun(sd0 + ss9, (mw0 >> 8) & 2u);
            float p10 = pfun(sd1 + ss0, mw1 & 1u);
            float p11 = pfun(sd1 + ss1, mw1 & 2u);
            float p18 = pfun(sd1 + ss8, (mw1 >> 8) & 1u);
            float p19 = pfun(sd1 + ss9, (mw1 >> 8) & 2u);
            z0 += (p00 + p01) + (p08 + p09);
            z1 += (p10 + p11) + (p18 + p19);

            unsigned a0 = bfpack(p01, p00), a1 = bfpack(p11, p10);
            unsigned a2 = bfpack(p09, p08), a3 = bfpack(p19, p18);
            unsigned e0 = bfpack(p01 - hif(a0), p00 - lowf(a0));
            unsigned e1 = bfpack(p11 - hif(a1), p10 - lowf(a1));
            unsigned e2 = bfpack(p09 - hif(a2), p08 - lowf(a2));
            unsigned e3 = bfpack(p19 - hif(a3), p18 - lowf(a3));

            const uint32_t rowhi = bhiB + (unsigned)(kk * 16 + l15) * 128u;
            const uint32_t rowlo = bloB + (unsigned)(kk * 16 + l15) * 128u;
#pragma unroll
            for (int nt = 0; nt < 8; nt++) {
                const unsigned coff = (unsigned)((nt ^ l7) << 4);
                uint32_t bh0, bh1, bl0, bl1;
                LDMX2T(bh0, bh1, rowhi + coff);
                LDMX2T(bl0, bl1, rowlo + coff);
                MMA(c[nt], a0, a1, a2, a3, bh0, bh1);
                MMA(c[nt], e0, e1, e2, e3, bh0, bh1);
                MMA(c[nt], a0, a1, a2, a3, bl0, bl1);
            }
        }
    }

    z0 += __shfl_xor_sync(0xffffffffu, z0, 1);
    z0 += __shfl_xor_sync(0xffffffffu, z0, 2);
    z1 += __shfl_xor_sync(0xffffffffu, z1, 1);
    z1 += __shfl_xor_sync(0xffffffffu, z1, 2);
    const float inv0 = 1.0f / z0, inv1 = 1.0f / z1;

    const size_t ro0 = (size_t)(i0 + rA0) * OD + h * 64;
    const size_t ro1 = (size_t)(i0 + rA1) * OD + h * 64;
#pragma unroll
    for (int nt = 0; nt < 8; nt++) {
        float v00 = c[nt][0] * inv0, v01 = c[nt][1] * inv0;
        float v10 = c[nt][2] * inv1, v11 = c[nt][3] * inv1;
        *(float2*)&g_hp[ro0 + nt * 8 + l3 * 2] = make_float2(v00, v01);
        *(float2*)&g_hp[ro1 + nt * 8 + l3 * 2] = make_float2(v10, v11);
        float s0 = v00 + v10, s1 = v01 + v11;
        float q0 = v00 * v00 + v10 * v10, q1 = v01 * v01 + v11 * v11;
#pragma unroll
        for (int d = 4; d < 32; d <<= 1) {
            s0 += __shfl_xor_sync(0xffffffffu, s0, d);
            s1 += __shfl_xor_sync(0xffffffffu, s1, d);
            q0 += __shfl_xor_sync(0xffffffffu, q0, d);
            q1 += __shfl_xor_sync(0xffffffffu, q1, d);
        }
        if (lane < 4) {
            colS[w * 64 + nt * 8 + lane * 2] = s0;
            colS[w * 64 + nt * 8 + lane * 2 + 1] = s1;
            colQ[w * 64 + nt * 8 + lane * 2] = q0;
            colQ[w * 64 + nt * 8 + lane * 2 + 1] = q1;
        }
    }
    __syncthreads();
    if (t < 64) {
        float s = 0.f, q = 0.f;
#pragma unroll
        for (int ww = 0; ww < 8; ww++) {
            s += colS[ww * 64 + t];
            q += colQ[ww * 64 + t];
        }
        g_cs[it * OD + h * 64 + t] = s;
        g_cq[it * OD + h * 64 + t] = q;
    }
}

// ================= Kernel E: column stats (parallel) =================
__global__ void __launch_bounds__(1024) colstats_kernel() {
    const int w = threadIdx.x >> 5, lane = threadIdx.x & 31;
    const int col = blockIdx.x * 32 + w;
    float s = g_cs[lane * OD + col];
    float q = g_cq[lane * OD + col];
#pragma unroll
    for (int d = 16; d >= 1; d >>= 1) {
        s += __shfl_xor_sync(0xffffffffu, s, d);
        q += __shfl_xor_sync(0xffffffffu, q, d);
    }
    if (lane == 0) {
        float mean = s * (1.0f / Nn);
        float var = q * (1.0f / Nn) - mean * mean;
        g_mean[col] = mean;
        g_rstd[col] = rsqrtf(var + EPSV);
    }
}

// ================= Kernel F: layernorm + relu =================
__global__ void __launch_bounds__(256) norm_relu_kernel(const float* __restrict__ gamma,
                                                        const float* __restrict__ beta,
                                                        float* __restrict__ out) {
    const int idx4 = blockIdx.x * 256 + threadIdx.x;
    const int basei = idx4 * 4;
    const int col = basei & (OD - 1);
    float4 xv = *(const float4*)&g_hp[basei];
    float4 mn = *(const float4*)&g_mean[col];
    float4 rs = *(const float4*)&g_rstd[col];
    float4 ga = *(const float4*)&gamma[col];
    float4 be = *(const float4*)&beta[col];
    float4 o;
    o.x = fmaxf(0.f, ga.x * (xv.x - mn.x) * rs.x + be.x);
    o.y = fmaxf(0.f, ga.y * (xv.y - mn.y) * rs.y + be.y);
    o.z = fmaxf(0.f, ga.z * (xv.z - mn.z) * rs.z + be.z);
    o.w = fmaxf(0.f, ga.w * (xv.w - mn.w) * rs.w + be.w);
    *(float4*)&out[basei] = o;
}

// ================= launch =================
extern "C" void kernel_launch(void* const* d_in, const int* in_sizes, int n_in,
                              void* d_out, int out_size) {
    const float* x     = (const float*)d_in[0];
    const int*   adj   = (const int*)d_in[1];
    const float* W     = (const float*)d_in[2];
    const float* a     = (const float*)d_in[3];
    const float* gamma = (const float*)d_in[4];
    const float* beta  = (const float*)d_in[5];
    float* out = (float*)d_out;

    gemm_xWt_kernel<<<dim3(OD / 64, Nn / 64), 256>>>(x, W);
    scores_kernel<<<(Nn * Hh) / 256, 256>>>(a);
    maskpack_kernel<<<Nn, 256>>>(adj);
    attn_mma_kernel<<<dim3(Hh, ITILES), 256>>>();
    colstats_kernel<<<OD / 32, 1024>>>();
    norm_relu_kernel<<<(Nn * OD / 4) / 256, 256>>>(gamma, beta, out);
}

// round 6
// speedup vs baseline: 5.1005x; 1.4240x over previous
#include <cuda_runtime.h>
#include <cuda_bf16.h>
#include <cstdint>

#define Nn 4096
#define IND 512
#define OD 512
#define Hh 8
#define Dd 64
#define ALPHA 0.2f
#define EPSV 1e-5f
#define LOG2E 1.4426950408889634f
#define ITILES 32
#define NTILES 32

__device__ __nv_bfloat16 g_xhi[Nn * IND], g_xlo[Nn * IND];
__device__ __nv_bfloat16 g_whi[OD * IND], g_wlo[OD * IND];
__device__ float g_Wh[Nn * OD];
__device__ __nv_bfloat16 g_Bhi[Nn * OD];   // bf16(Wh) hi, [i][o]
__device__ __nv_bfloat16 g_Blo[Nn * OD];   // residual lo, [i][o]
__device__ float g_sdL[Hh * Nn], g_ssL[Hh * Nn];   // scores * log2(e)
__device__ unsigned g_mask[Nn * (Nn / 32)];
__device__ float g_hp[Nn * OD];
__device__ float g_cs[ITILES * OD], g_cq[ITILES * OD];
__device__ float g_mean[OD], g_rstd[OD];

__device__ __forceinline__ unsigned bfpack(float hi, float lo) {
    unsigned r;
    asm("cvt.rn.bf16x2.f32 %0, %1, %2;" : "=r"(r) : "f"(hi), "f"(lo));
    return r;
}
__device__ __forceinline__ float lowf(unsigned u) { return __uint_as_float(u << 16); }
__device__ __forceinline__ float hif(unsigned u) { return __uint_as_float(u & 0xffff0000u); }
__device__ __forceinline__ float ex2f(float x) {
    float r;
    asm("ex2.approx.ftz.f32 %0, %1;" : "=f"(r) : "f"(x));
    return r;
}
__device__ __forceinline__ uint32_t smem_u32(const void* p) {
    uint32_t a;
    asm("{ .reg .u64 t; cvta.to.shared.u64 t, %1; cvt.u32.u64 %0, t; }" : "=r"(a) : "l"(p));
    return a;
}
__device__ __forceinline__ float pfun(float tL, unsigned bit) {
    float g = fmaxf(tL, ALPHA * tL);
    float p = ex2f(g);
    return bit ? p : 0.f;
}

#define MMA(cc, A0, A1, A2, A3, B0, B1)                                            \
    asm volatile("mma.sync.aligned.m16n8k16.row.col.f32.bf16.bf16.f32 "            \
                 "{%0,%1,%2,%3},{%4,%5,%6,%7},{%8,%9},{%0,%1,%2,%3};"              \
                 : "+f"(cc[0]), "+f"(cc[1]), "+f"(cc[2]), "+f"(cc[3])              \
                 : "r"(A0), "r"(A1), "r"(A2), "r"(A3), "r"(B0), "r"(B1))

#define LDMX4T(r0, r1, r2, r3, addr)                                               \
    asm volatile("ldmatrix.sync.aligned.m8n8.x4.trans.shared.b16 {%0,%1,%2,%3},[%4];" \
                 : "=r"(r0), "=r"(r1), "=r"(r2), "=r"(r3) : "r"(addr))

#define LDMX4(r0, r1, r2, r3, addr)                                                \
    asm volatile("ldmatrix.sync.aligned.m8n8.x4.shared.b16 {%0,%1,%2,%3},[%4];"    \
                 : "=r"(r0), "=r"(r1), "=r"(r2), "=r"(r3) : "r"(addr))

#define CPA16(dst, src)                                                            \
    asm volatile("cp.async.cg.shared.global [%0], [%1], 16;" :: "r"(dst), "l"(src) : "memory")
#define CPCOMMIT() asm volatile("cp.async.commit_group;" ::: "memory")
#define CPWAIT(N) asm volatile("cp.async.wait_group %0;" :: "n"(N) : "memory")

// ================= Kernel P: fp32 -> bf16 hi/lo convert =================
__global__ void __launch_bounds__(256) cvt_kernel(const float* __restrict__ src,
                                                  __nv_bfloat16* __restrict__ hi,
                                                  __nv_bfloat16* __restrict__ lo) {
    const int i4 = (blockIdx.x * 256 + threadIdx.x) * 4;
    float4 v = *(const float4*)&src[i4];
    unsigned h01 = bfpack(v.y, v.x), h23 = bfpack(v.w, v.z);
    unsigned l01 = bfpack(v.y - hif(h01), v.x - lowf(h01));
    unsigned l23 = bfpack(v.w - hif(h23), v.z - lowf(h23));
    *(uint2*)&hi[i4] = make_uint2(h01, h23);
    *(uint2*)&lo[i4] = make_uint2(l01, l23);
}

// ================= Kernel A: Wh = x @ W^T via HMMA (split x, split W) =================
// CTA: 128 i-rows x 64 o-cols. grid (8, 32). smem: xhi/xlo [128][64], whi/wlo [64][64].
#define GXHI 0
#define GXLO 16384
#define GWHI 32768
#define GWLO 40960
#define SMEM_GEMM 49152

__global__ void __launch_bounds__(256, 2) gemm_mma_kernel() {
    extern __shared__ char dsm[];
    const uint32_t smb = smem_u32(dsm);
    const int o0 = blockIdx.x * 64, i0 = blockIdx.y * 128;
    const int t = threadIdx.x, w = t >> 5, lane = t & 31;
    const int l3 = lane & 3, l7 = lane & 7, l15 = lane & 15;

    float c[8][4];
#pragma unroll
    for (int nt = 0; nt < 8; nt++)
#pragma unroll
        for (int q = 0; q < 4; q++) c[nt][q] = 0.f;

    for (int ch = 0; ch < 8; ch++) {
        const int k0 = ch * 64;
#pragma unroll
        for (int q = 0; q < 4; q++) {
            int idx = t + q * 256;
            int i = idx >> 3, cc = idx & 7;
            unsigned so = (unsigned)i * 128u + (unsigned)((cc ^ (i & 7)) << 4);
            const size_t gof = (size_t)(i0 + i) * IND + k0 + cc * 8;
            CPA16(smb + GXHI + so, &g_xhi[gof]);
            CPA16(smb + GXLO + so, &g_xlo[gof]);
        }
#pragma unroll
        for (int q = 0; q < 2; q++) {
            int idx = t + q * 256;
            int o = idx >> 3, cc = idx & 7;
            unsigned so = (unsigned)o * 128u + (unsigned)((cc ^ (o & 7)) << 4);
            const size_t gof = (size_t)(o0 + o) * IND + k0 + cc * 8;
            CPA16(smb + GWHI + so, &g_whi[gof]);
            CPA16(smb + GWLO + so, &g_wlo[gof]);
        }
        CPCOMMIT();
        CPWAIT(0);
        __syncthreads();

#pragma unroll
        for (int ks = 0; ks < 4; ks++) {
            uint32_t arow = smb + GXHI + (unsigned)(w * 16 + l15) * 128u +
                            (((unsigned)(2 * ks + (lane >> 4)) ^ (unsigned)l7) << 4);
            uint32_t ah0, ah1, ah2, ah3, al0, al1, al2, al3;
            LDMX4(ah0, ah1, ah2, ah3, arow);
            LDMX4(al0, al1, al2, al3, arow + 16384);
#pragma unroll
            for (int np = 0; np < 4; np++) {
                uint32_t brow = smb + GWHI +
                                (unsigned)(np * 16 + (lane >> 4) * 8 + l7) * 128u +
                                (((unsigned)(2 * ks + ((lane >> 3) & 1)) ^ (unsigned)l7) << 4);
                uint32_t bh0, bh1, bh2, bh3, bl0, bl1, bl2, bl3;
                LDMX4(bh0, bh1, bh2, bh3, brow);
                LDMX4(bl0, bl1, bl2, bl3, brow + 8192);
                MMA(c[2 * np], ah0, ah1, ah2, ah3, bh0, bh1);
                MMA(c[2 * np], al0, al1, al2, al3, bh0, bh1);
                MMA(c[2 * np], ah0, ah1, ah2, ah3, bl0, bl1);
                MMA(c[2 * np + 1], ah0, ah1, ah2, ah3, bh2, bh3);
                MMA(c[2 * np + 1], al0, al1, al2, al3, bh2, bh3);
                MMA(c[2 * np + 1], ah0, ah1, ah2, ah3, bl2, bl3);
            }
        }
        __syncthreads();
    }

    const int rA0 = w * 16 + (lane >> 2), rA1 = rA0 + 8;
#pragma unroll
    for (int nt = 0; nt < 8; nt++) {
        const int col = o0 + nt * 8 + l3 * 2;
        const size_t f0 = (size_t)(i0 + rA0) * OD + col;
        const size_t f1 = (size_t)(i0 + rA1) * OD + col;
        float v00 = c[nt][0], v01 = c[nt][1], v10 = c[nt][2], v11 = c[nt][3];
        *(float2*)&g_Wh[f0] = make_float2(v00, v01);
        *(float2*)&g_Wh[f1] = make_float2(v10, v11);
        unsigned h0 = bfpack(v01, v00), h1 = bfpack(v11, v10);
        *(unsigned*)&g_Bhi[f0] = h0;
        *(unsigned*)&g_Bhi[f1] = h1;
        *(unsigned*)&g_Blo[f0] = bfpack(v01 - hif(h0), v00 - lowf(h0));
        *(unsigned*)&g_Blo[f1] = bfpack(v11 - hif(h1), v10 - lowf(h1));
    }
}

// ================= Kernel B: adj -> bitmask =================
__global__ void __launch_bounds__(256) maskpack_kernel(const int* __restrict__ adj) {
    const int row = blockIdx.x;
    const int w = threadIdx.x >> 5, lane = threadIdx.x & 31;
    const int* arow = adj + (size_t)row * Nn;
#pragma unroll
    for (int k = 0; k < 16; k++) {
        int word = w * 16 + k;
        unsigned bal = __ballot_sync(0xffffffffu, arow[word * 32 + lane] > 0);
        if (lane == 0) g_mask[row * 128 + word] = bal;
    }
}

// ================= Kernel C: scores (prescaled by log2 e) =================
__global__ void __launch_bounds__(256) scores_kernel(const float* __restrict__ a) {
    const int t = blockIdx.x * 256 + threadIdx.x;
    const int j = t >> 3, h = t & 7;
    const float* wrow = &g_Wh[(size_t)j * OD + h * Dd];
    float ssrc = 0.f, sdst = 0.f;
#pragma unroll
    for (int d = 0; d < Dd; d += 4) {
        float4 wv = *(const float4*)&wrow[d];
        float4 as = *(const float4*)&a[d];
        float4 ad = *(const float4*)&a[Dd + d];
        ssrc += wv.x * as.x + wv.y * as.y + wv.z * as.z + wv.w * as.w;
        sdst += wv.x * ad.x + wv.y * ad.y + wv.z * ad.z + wv.w * ad.w;
    }
    g_ssL[h * Nn + j] = ssrc * LOG2E;
    g_sdL[h * Nn + j] = sdst * LOG2E;
}

// ================= Kernel D: HMMA attention aggregation (cp.async pipelined) =================
#define BUFSZ 36864
#define BLO_O 16384
#define MSK_O 32768
#define SSL_O 34816
#define COLS_O 73728
#define COLQ_O 75776
#define SMEM_ATTN 77824

__device__ __forceinline__ void attn_issue(uint32_t smb, int b, int h, int i0, int j0, int t) {
    const uint32_t bb = smb + (unsigned)b * BUFSZ;
#pragma unroll
    for (int q = 0; q < 4; q++) {
        int idx = t + q * 256;
        int j = idx >> 3, cc = idx & 7;
        unsigned so = (unsigned)j * 128u + (unsigned)((cc ^ (j & 7)) << 4);
        const size_t gof = (size_t)(j0 + j) * OD + h * 64 + cc * 8;
        CPA16(bb + so, &g_Bhi[gof]);
        CPA16(bb + BLO_O + so, &g_Blo[gof]);
    }
    if (t < 128) CPA16(bb + MSK_O + t * 16, &g_mask[(size_t)(i0 + t) * 128 + (j0 >> 5)]);
    if (t < 32) CPA16(bb + SSL_O + t * 16, &g_ssL[h * Nn + j0 + t * 4]);
}

__global__ void __launch_bounds__(256, 2) attn_mma_kernel() {
    extern __shared__ char dsm[];
    const uint32_t smb = smem_u32(dsm);

    const int h = blockIdx.x, it = blockIdx.y, i0 = it * 128;
    const int t = threadIdx.x, w = t >> 5, lane = t & 31;
    const int l3 = lane & 3, l7 = lane & 7, l15 = lane & 15;
    const int rA0 = w * 16 + (lane >> 2), rA1 = rA0 + 8;
    const float sd0 = g_sdL[h * Nn + i0 + rA0];
    const float sd1 = g_sdL[h * Nn + i0 + rA1];

    float z0 = 0.f, z1 = 0.f;
    float c[8][4];
#pragma unroll
    for (int nt = 0; nt < 8; nt++)
#pragma unroll
        for (int q = 0; q < 4; q++) c[nt][q] = 0.f;

    attn_issue(smb, 0, h, i0, 0, t);
    CPCOMMIT();

    for (int tl = 0; tl < NTILES; tl++) {
        if (tl < NTILES - 1) {
            attn_issue(smb, (tl + 1) & 1, h, i0, (tl + 1) * 128, t);
            CPCOMMIT();
            CPWAIT(1);
        } else {
            CPWAIT(0);
        }
        __syncthreads();

        const uint32_t bb = smb + (unsigned)(tl & 1) * BUFSZ;
        const char* bpd = dsm + (tl & 1) * BUFSZ;

#pragma unroll
        for (int kk = 0; kk < 8; kk++) {
            const int jc = kk * 16 + l3 * 2;
            const float2 sA = *(const float2*)(bpd + SSL_O + jc * 4);
            const float2 sB = *(const float2*)(bpd + SSL_O + (jc + 8) * 4);
            const unsigned sh = (kk & 1) * 16 + l3 * 2;
            const unsigned mw0 =
                (*(const unsigned*)(bpd + MSK_O + rA0 * 16 + ((kk >> 1) << 2))) >> sh;
            const unsigned mw1 =
                (*(const unsigned*)(bpd + MSK_O + rA1 * 16 + ((kk >> 1) << 2))) >> sh;

            float p00 = pfun(sd0 + sA.x, mw0 & 1u);
            float p01 = pfun(sd0 + sA.y, mw0 & 2u);
            float p08 = pfun(sd0 + sB.x, (mw0 >> 8) & 1u);
            float p09 = pfun(sd0 + sB.y, (mw0 >> 8) & 2u);
            float p10 = pfun(sd1 + sA.x, mw1 & 1u);
            float p11 = pfun(sd1 + sA.y, mw1 & 2u);
            float p18 = pfun(sd1 + sB.x, (mw1 >> 8) & 1u);
            float p19 = pfun(sd1 + sB.y, (mw1 >> 8) & 2u);
            z0 += (p00 + p01) + (p08 + p09);
            z1 += (p10 + p11) + (p18 + p19);

            unsigned a0 = bfpack(p01, p00), a1 = bfpack(p11, p10);
            unsigned a2 = bfpack(p09, p08), a3 = bfpack(p19, p18);
            unsigned e0 = bfpack(p01 - hif(a0), p00 - lowf(a0));
            unsigned e1 = bfpack(p11 - hif(a1), p10 - lowf(a1));
            unsigned e2 = bfpack(p09 - hif(a2), p08 - lowf(a2));
            unsigned e3 = bfpack(p19 - hif(a3), p18 - lowf(a3));

            const unsigned rowoff = (unsigned)(kk * 16 + l15) * 128u;
#pragma unroll
            for (int np = 0; np < 4; np++) {
                const unsigned chn =
                    (((unsigned)(np * 2 + (lane >> 4)) ^ (unsigned)l7) << 4);
                const uint32_t ahx = bb + rowoff + chn;
                uint32_t bh0, bh1, bh2, bh3, bl0, bl1, bl2, bl3;
                LDMX4T(bh0, bh1, bh2, bh3, ahx);
                LDMX4T(bl0, bl1, bl2, bl3, ahx + BLO_O);
                MMA(c[2 * np], a0, a1, a2, a3, bh0, bh1);
                MMA(c[2 * np], e0, e1, e2, e3, bh0, bh1);
                MMA(c[2 * np], a0, a1, a2, a3, bl0, bl1);
                MMA(c[2 * np + 1], a0, a1, a2, a3, bh2, bh3);
                MMA(c[2 * np + 1], e0, e1, e2, e3, bh2, bh3);
                MMA(c[2 * np + 1], a0, a1, a2, a3, bl2, bl3);
            }
        }
        __syncthreads();
    }

    z0 += __shfl_xor_sync(0xffffffffu, z0, 1);
    z0 += __shfl_xor_sync(0xffffffffu, z0, 2);
    z1 += __shfl_xor_sync(0xffffffffu, z1, 1);
    z1 += __shfl_xor_sync(0xffffffffu, z1, 2);
    const float inv0 = 1.0f / z0, inv1 = 1.0f / z1;

    float* colS = (float*)(dsm + COLS_O);
    float* colQ = (float*)(dsm + COLQ_O);

    const size_t ro0 = (size_t)(i0 + rA0) * OD + h * 64;
    const size_t ro1 = (size_t)(i0 + rA1) * OD + h * 64;
#pragma unroll
    for (int nt = 0; nt < 8; nt++) {
        float v00 = c[nt][0] * inv0, v01 = c[nt][1] * inv0;
        float v10 = c[nt][2] * inv1, v11 = c[nt][3] * inv1;
        *(float2*)&g_hp[ro0 + nt * 8 + l3 * 2] = make_float2(v00, v01);
        *(float2*)&g_hp[ro1 + nt * 8 + l3 * 2] = make_float2(v10, v11);
        float s0 = v00 + v10, s1 = v01 + v11;
        float q0 = v00 * v00 + v10 * v10, q1 = v01 * v01 + v11 * v11;
#pragma unroll
        for (int d = 4; d < 32; d <<= 1) {
            s0 += __shfl_xor_sync(0xffffffffu, s0, d);
            s1 += __shfl_xor_sync(0xffffffffu, s1, d);
            q0 += __shfl_xor_sync(0xffffffffu, q0, d);
            q1 += __shfl_xor_sync(0xffffffffu, q1, d);
        }
        if (lane < 4) {
            colS[w * 64 + nt * 8 + lane * 2] = s0;
            colS[w * 64 + nt * 8 + lane * 2 + 1] = s1;
            colQ[w * 64 + nt * 8 + lane * 2] = q0;
            colQ[w * 64 + nt * 8 + lane * 2 + 1] = q1;
        }
    }
    __syncthreads();
    if (t < 64) {
        float s = 0.f, q = 0.f;
#pragma unroll
        for (int ww = 0; ww < 8; ww++) {
            s += colS[ww * 64 + t];
            q += colQ[ww * 64 + t];
        }
        g_cs[it * OD + h * 64 + t] = s;
        g_cq[it * OD + h * 64 + t] = q;
    }
}

// ================= Kernel E: column stats (parallel) =================
__global__ void __launch_bounds__(1024) colstats_kernel() {
    const int w = threadIdx.x >> 5, lane = threadIdx.x & 31;
    const int col = blockIdx.x * 32 + w;
    float s = g_cs[lane * OD + col];
    float q = g_cq[lane * OD + col];
#pragma unroll
    for (int d = 16; d >= 1; d >>= 1) {
        s += __shfl_xor_sync(0xffffffffu, s, d);
        q += __shfl_xor_sync(0xffffffffu, q, d);
    }
    if (lane == 0) {
        float mean = s * (1.0f / Nn);
        float var = q * (1.0f / Nn) - mean * mean;
        g_mean[col] = mean;
        g_rstd[col] = rsqrtf(var + EPSV);
    }
}

// ================= Kernel F: layernorm + relu =================
__global__ void __launch_bounds__(256) norm_relu_kernel(const float* __restrict__ gamma,
                                                        const float* __restrict__ beta,
                                                        float* __restrict__ out) {
    const int idx4 = blockIdx.x * 256 + threadIdx.x;
    const int basei = idx4 * 4;
    const int col = basei & (OD - 1);
    float4 xv = *(const float4*)&g_hp[basei];
    float4 mn = *(const float4*)&g_mean[col];
    float4 rs = *(const float4*)&g_rstd[col];
    float4 ga = *(const float4*)&gamma[col];
    float4 be = *(const float4*)&beta[col];
    float4 o;
    o.x = fmaxf(0.f, ga.x * (xv.x - mn.x) * rs.x + be.x);
    o.y = fmaxf(0.f, ga.y * (xv.y - mn.y) * rs.y + be.y);
    o.z = fmaxf(0.f, ga.z * (xv.z - mn.z) * rs.z + be.z);
    o.w = fmaxf(0.f, ga.w * (xv.w - mn.w) * rs.w + be.w);
    *(float4*)&out[basei] = o;
}

// ================= launch =================
extern "C" void kernel_launch(void* const* d_in, const int* in_sizes, int n_in,
                              void* d_out, int out_size) {
    const float* x     = (const float*)d_in[0];
    const int*   adj   = (const int*)d_in[1];
    const float* W     = (const float*)d_in[2];
    const float* a     = (const float*)d_in[3];
    const float* gamma = (const float*)d_in[4];
    const float* beta  = (const float*)d_in[5];
    float* out = (float*)d_out;

    static int attrs_set = 0;
    if (!attrs_set) {
        cudaFuncSetAttribute(attn_mma_kernel,
                             cudaFuncAttributeMaxDynamicSharedMemorySize, SMEM_ATTN);
        cudaFuncSetAttribute(gemm_mma_kernel,
                             cudaFuncAttributeMaxDynamicSharedMemorySize, SMEM_GEMM);
        attrs_set = 1;
    }

    __nv_bfloat16* xhi;
    cvt_kernel<<<(Nn * IND / 4) / 256, 256>>>(x, (cudaGetSymbolAddress((void**)&xhi, g_xhi), xhi),
                                              (cudaGetSymbolAddress((void**)&xhi, g_xlo), xhi));
    __nv_bfloat16* whi;
    cvt_kernel<<<(OD * IND / 4) / 256, 256>>>(W, (cudaGetSymbolAddress((void**)&whi, g_whi), whi),
                                              (cudaGetSymbolAddress((void**)&whi, g_wlo), whi));
    gemm_mma_kernel<<<dim3(OD / 64, Nn / 128), 256, SMEM_GEMM>>>();
    scores_kernel<<<(Nn * Hh) / 256, 256>>>(a);
    maskpack_kernel<<<Nn, 256>>>(adj);
    attn_mma_kernel<<<dim3(Hh, ITILES), 256, SMEM_ATTN>>>();
    colstats_kernel<<<OD / 32, 1024>>>();
    norm_relu_kernel<<<(Nn * OD / 4) / 256, 256>>>(gamma, beta, out);
}

// round 7
// speedup vs baseline: 5.1112x; 1.0021x over previous
#include <cuda_runtime.h>
#include <cuda_bf16.h>
#include <cstdint>

#define Nn 4096
#define IND 512
#define OD 512
#define Hh 8
#define Dd 64
#define ALPHA 0.2f
#define EPSV 1e-5f
#define LOG2E 1.4426950408889634f
#define ITILES 32
#define NTILES 32

__device__ __nv_bfloat16 g_xhi[Nn * IND], g_xlo[Nn * IND];
__device__ __nv_bfloat16 g_whi[OD * IND], g_wlo[OD * IND];
__device__ float g_Wh[Nn * OD];
__device__ __nv_bfloat16 g_Bhi[Nn * OD];   // bf16(Wh) hi, [i][o]
__device__ __nv_bfloat16 g_Blo[Nn * OD];   // residual lo, [i][o]
__device__ float g_sdL[Hh * Nn], g_ssL[Hh * Nn];   // scores * log2(e)
__device__ unsigned g_mask[Nn * (Nn / 32)];
__device__ float g_hp[Nn * OD];
__device__ float g_cs[ITILES * OD], g_cq[ITILES * OD];
__device__ float g_mean[OD], g_rstd[OD];

__device__ __forceinline__ unsigned bfpack(float hi, float lo) {
    unsigned r;
    asm("cvt.rn.bf16x2.f32 %0, %1, %2;" : "=r"(r) : "f"(hi), "f"(lo));
    return r;
}
__device__ __forceinline__ float lowf(unsigned u) { return __uint_as_float(u << 16); }
__device__ __forceinline__ float hif(unsigned u) { return __uint_as_float(u & 0xffff0000u); }
__device__ __forceinline__ float ex2f(float x) {
    float r;
    asm("ex2.approx.ftz.f32 %0, %1;" : "=f"(r) : "f"(x));
    return r;
}
__device__ __forceinline__ uint32_t smem_u32(const void* p) {
    uint32_t a;
    asm("{ .reg .u64 t; cvta.to.shared.u64 t, %1; cvt.u32.u64 %0, t; }" : "=r"(a) : "l"(p));
    return a;
}
__device__ __forceinline__ float pfun(float tL, unsigned bit) {
    float g = fmaxf(tL, ALPHA * tL);
    float p = ex2f(g);
    return bit ? p : 0.f;
}

#define MMA(cc, A0, A1, A2, A3, B0, B1)                                            \
    asm volatile("mma.sync.aligned.m16n8k16.row.col.f32.bf16.bf16.f32 "            \
                 "{%0,%1,%2,%3},{%4,%5,%6,%7},{%8,%9},{%0,%1,%2,%3};"              \
                 : "+f"(cc[0]), "+f"(cc[1]), "+f"(cc[2]), "+f"(cc[3])              \
                 : "r"(A0), "r"(A1), "r"(A2), "r"(A3), "r"(B0), "r"(B1))

#define LDMX4T(r0, r1, r2, r3, addr)                                               \
    asm volatile("ldmatrix.sync.aligned.m8n8.x4.trans.shared.b16 {%0,%1,%2,%3},[%4];" \
                 : "=r"(r0), "=r"(r1), "=r"(r2), "=r"(r3) : "r"(addr))

#define LDMX4(r0, r1, r2, r3, addr)                                                \
    asm volatile("ldmatrix.sync.aligned.m8n8.x4.shared.b16 {%0,%1,%2,%3},[%4];"    \
                 : "=r"(r0), "=r"(r1), "=r"(r2), "=r"(r3) : "r"(addr))

#define CPA16(dst, src)                                                            \
    asm volatile("cp.async.cg.shared.global [%0], [%1], 16;" :: "r"(dst), "l"(src) : "memory")
#define CPCOMMIT() asm volatile("cp.async.commit_group;" ::: "memory")
#define CPWAIT(N) asm volatile("cp.async.wait_group %0;" :: "n"(N) : "memory")

// ================= Kernel P: fp32 -> bf16 hi/lo convert =================
__global__ void __launch_bounds__(256) cvt_kernel(const float* __restrict__ src,
                                                  __nv_bfloat16* __restrict__ hi,
                                                  __nv_bfloat16* __restrict__ lo) {
    const int i4 = (blockIdx.x * 256 + threadIdx.x) * 4;
    float4 v = *(const float4*)&src[i4];
    unsigned h01 = bfpack(v.y, v.x), h23 = bfpack(v.w, v.z);
    unsigned l01 = bfpack(v.y - hif(h01), v.x - lowf(h01));
    unsigned l23 = bfpack(v.w - hif(h23), v.z - lowf(h23));
    *(uint2*)&hi[i4] = make_uint2(h01, h23);
    *(uint2*)&lo[i4] = make_uint2(l01, l23);
}

// ================= Kernel A: Wh = x @ W^T via HMMA, double-buffered =================
// CTA: 128 i-rows x 64 o-cols. Buffer (48KB): xhi/xlo [128][64], whi/wlo [64][64].
#define GXHI 0
#define GXLO 16384
#define GWHI 32768
#define GWLO 40960
#define GBUF 49152
#define SMEM_GEMM (2 * GBUF)

__device__ __forceinline__ void gemm_issue(uint32_t smb, int buf, int i0, int o0, int k0, int t) {
    const uint32_t bb = smb + (unsigned)buf * GBUF;
#pragma unroll
    for (int q = 0; q < 4; q++) {
        int idx = t + q * 256;
        int i = idx >> 3, cc = idx & 7;
        unsigned so = (unsigned)i * 128u + (unsigned)((cc ^ (i & 7)) << 4);
        const size_t gof = (size_t)(i0 + i) * IND + k0 + cc * 8;
        CPA16(bb + GXHI + so, &g_xhi[gof]);
        CPA16(bb + GXLO + so, &g_xlo[gof]);
    }
#pragma unroll
    for (int q = 0; q < 2; q++) {
        int idx = t + q * 256;
        int o = idx >> 3, cc = idx & 7;
        unsigned so = (unsigned)o * 128u + (unsigned)((cc ^ (o & 7)) << 4);
        const size_t gof = (size_t)(o0 + o) * IND + k0 + cc * 8;
        CPA16(bb + GWHI + so, &g_whi[gof]);
        CPA16(bb + GWLO + so, &g_wlo[gof]);
    }
}

__global__ void __launch_bounds__(256, 2) gemm_mma_kernel() {
    extern __shared__ char dsm[];
    const uint32_t smb = smem_u32(dsm);
    const int o0 = blockIdx.x * 64, i0 = blockIdx.y * 128;
    const int t = threadIdx.x, w = t >> 5, lane = t & 31;
    const int l3 = lane & 3, l7 = lane & 7, l15 = lane & 15;

    float c[8][4];
#pragma unroll
    for (int nt = 0; nt < 8; nt++)
#pragma unroll
        for (int q = 0; q < 4; q++) c[nt][q] = 0.f;

    gemm_issue(smb, 0, i0, o0, 0, t);
    CPCOMMIT();

    for (int ch = 0; ch < 8; ch++) {
        if (ch < 7) {
            gemm_issue(smb, (ch + 1) & 1, i0, o0, (ch + 1) * 64, t);
            CPCOMMIT();
            CPWAIT(1);
        } else {
            CPWAIT(0);
        }
        __syncthreads();
        const uint32_t bb = smb + (unsigned)(ch & 1) * GBUF;

#pragma unroll
        for (int ks = 0; ks < 4; ks++) {
            uint32_t arow = bb + GXHI + (unsigned)(w * 16 + l15) * 128u +
                            (((unsigned)(2 * ks + (lane >> 4)) ^ (unsigned)l7) << 4);
            uint32_t ah0, ah1, ah2, ah3, al0, al1, al2, al3;
            LDMX4(ah0, ah1, ah2, ah3, arow);
            LDMX4(al0, al1, al2, al3, arow + 16384);
#pragma unroll
            for (int np = 0; np < 4; np++) {
                uint32_t brow = bb + GWHI +
                                (unsigned)(np * 16 + (lane >> 4) * 8 + l7) * 128u +
                                (((unsigned)(2 * ks + ((lane >> 3) & 1)) ^ (unsigned)l7) << 4);
                uint32_t bh0, bh1, bh2, bh3, bl0, bl1, bl2, bl3;
                LDMX4(bh0, bh1, bh2, bh3, brow);
                LDMX4(bl0, bl1, bl2, bl3, brow + 8192);
                MMA(c[2 * np], ah0, ah1, ah2, ah3, bh0, bh1);
                MMA(c[2 * np], al0, al1, al2, al3, bh0, bh1);
                MMA(c[2 * np], ah0, ah1, ah2, ah3, bl0, bl1);
                MMA(c[2 * np + 1], ah0, ah1, ah2, ah3, bh2, bh3);
                MMA(c[2 * np + 1], al0, al1, al2, al3, bh2, bh3);
                MMA(c[2 * np + 1], ah0, ah1, ah2, ah3, bl2, bl3);
            }
        }
        __syncthreads();
    }

    const int rA0 = w * 16 + (lane >> 2), rA1 = rA0 + 8;
#pragma unroll
    for (int nt = 0; nt < 8; nt++) {
        const int col = o0 + nt * 8 + l3 * 2;
        const size_t f0 = (size_t)(i0 + rA0) * OD + col;
        const size_t f1 = (size_t)(i0 + rA1) * OD + col;
        float v00 = c[nt][0], v01 = c[nt][1], v10 = c[nt][2], v11 = c[nt][3];
        *(float2*)&g_Wh[f0] = make_float2(v00, v01);
        *(float2*)&g_Wh[f1] = make_float2(v10, v11);
        unsigned h0 = bfpack(v01, v00), h1 = bfpack(v11, v10);
        *(unsigned*)&g_Bhi[f0] = h0;
        *(unsigned*)&g_Bhi[f1] = h1;
        *(unsigned*)&g_Blo[f0] = bfpack(v01 - hif(h0), v00 - lowf(h0));
        *(unsigned*)&g_Blo[f1] = bfpack(v11 - hif(h1), v10 - lowf(h1));
    }
}

// ================= Kernel B: adj -> bitmask =================
__global__ void __launch_bounds__(256) maskpack_kernel(const int* __restrict__ adj) {
    const int row = blockIdx.x;
    const int w = threadIdx.x >> 5, lane = threadIdx.x & 31;
    const int* arow = adj + (size_t)row * Nn;
#pragma unroll
    for (int k = 0; k < 16; k++) {
        int word = w * 16 + k;
        unsigned bal = __ballot_sync(0xffffffffu, arow[word * 32 + lane] > 0);
        if (lane == 0) g_mask[row * 128 + word] = bal;
    }
}

// ================= Kernel C: scores (prescaled by log2 e) =================
__global__ void __launch_bounds__(256) scores_kernel(const float* __restrict__ a) {
    const int t = blockIdx.x * 256 + threadIdx.x;
    const int j = t >> 3, h = t & 7;
    const float* wrow = &g_Wh[(size_t)j * OD + h * Dd];
    float ssrc = 0.f, sdst = 0.f;
#pragma unroll
    for (int d = 0; d < Dd; d += 4) {
        float4 wv = *(const float4*)&wrow[d];
        float4 as = *(const float4*)&a[d];
        float4 ad = *(const float4*)&a[Dd + d];
        ssrc += wv.x * as.x + wv.y * as.y + wv.z * as.z + wv.w * as.w;
        sdst += wv.x * ad.x + wv.y * ad.y + wv.z * ad.z + wv.w * ad.w;
    }
    g_ssL[h * Nn + j] = ssrc * LOG2E;
    g_sdL[h * Nn + j] = sdst * LOG2E;
}

// ================= Kernel D: HMMA attention, cp.async + P-fragment pipeline =================
#define BUFSZ 36864
#define BLO_O 16384
#define MSK_O 32768
#define SSL_O 34816
#define COLS_O 73728
#define COLQ_O 75776
#define SMEM_ATTN 77824

struct PFrag {
    unsigned a0, a1, a2, a3, e0, e1, e2, e3;
};

__device__ __forceinline__ PFrag make_frag(const char* bpd, int kk, int rA0, int rA1,
                                           float sd0, float sd1, int l3,
                                           float& z0, float& z1) {
    const int jc = kk * 16 + l3 * 2;
    const float2 sA = *(const float2*)(bpd + SSL_O + jc * 4);
    const float2 sB = *(const float2*)(bpd + SSL_O + (jc + 8) * 4);
    const unsigned sh = (kk & 1) * 16 + l3 * 2;
    const unsigned mw0 = (*(const unsigned*)(bpd + MSK_O + rA0 * 16 + ((kk >> 1) << 2))) >> sh;
    const unsigned mw1 = (*(const unsigned*)(bpd + MSK_O + rA1 * 16 + ((kk >> 1) << 2))) >> sh;

    float p00 = pfun(sd0 + sA.x, mw0 & 1u);
    float p01 = pfun(sd0 + sA.y, mw0 & 2u);
    float p08 = pfun(sd0 + sB.x, (mw0 >> 8) & 1u);
    float p09 = pfun(sd0 + sB.y, (mw0 >> 8) & 2u);
    float p10 = pfun(sd1 + sA.x, mw1 & 1u);
    float p11 = pfun(sd1 + sA.y, mw1 & 2u);
    float p18 = pfun(sd1 + sB.x, (mw1 >> 8) & 1u);
    float p19 = pfun(sd1 + sB.y, (mw1 >> 8) & 2u);
    z0 += (p00 + p01) + (p08 + p09);
    z1 += (p10 + p11) + (p18 + p19);

    PFrag f;
    f.a0 = bfpack(p01, p00);
    f.a1 = bfpack(p11, p10);
    f.a2 = bfpack(p09, p08);
    f.a3 = bfpack(p19, p18);
    f.e0 = bfpack(p01 - hif(f.a0), p00 - lowf(f.a0));
    f.e1 = bfpack(p11 - hif(f.a1), p10 - lowf(f.a1));
    f.e2 = bfpack(p09 - hif(f.a2), p08 - lowf(f.a2));
    f.e3 = bfpack(p19 - hif(f.a3), p18 - lowf(f.a3));
    return f;
}

__device__ __forceinline__ void attn_issue(uint32_t smb, int b, int h, int i0, int j0, int t) {
    const uint32_t bb = smb + (unsigned)b * BUFSZ;
#pragma unroll
    for (int q = 0; q < 4; q++) {
        int idx = t + q * 256;
        int j = idx >> 3, cc = idx & 7;
        unsigned so = (unsigned)j * 128u + (unsigned)((cc ^ (j & 7)) << 4);
        const size_t gof = (size_t)(j0 + j) * OD + h * 64 + cc * 8;
        CPA16(bb + so, &g_Bhi[gof]);
        CPA16(bb + BLO_O + so, &g_Blo[gof]);
    }
    if (t < 128) CPA16(bb + MSK_O + t * 16, &g_mask[(size_t)(i0 + t) * 128 + (j0 >> 5)]);
    if (t < 32) CPA16(bb + SSL_O + t * 16, &g_ssL[h * Nn + j0 + t * 4]);
}

__global__ void __launch_bounds__(256, 2) attn_mma_kernel() {
    extern __shared__ char dsm[];
    const uint32_t smb = smem_u32(dsm);

    const int h = blockIdx.x, it = blockIdx.y, i0 = it * 128;
    const int t = threadIdx.x, w = t >> 5, lane = t & 31;
    const int l3 = lane & 3, l7 = lane & 7, l15 = lane & 15;
    const int rA0 = w * 16 + (lane >> 2), rA1 = rA0 + 8;
    const float sd0 = g_sdL[h * Nn + i0 + rA0];
    const float sd1 = g_sdL[h * Nn + i0 + rA1];

    float z0 = 0.f, z1 = 0.f;
    float c[8][4];
#pragma unroll
    for (int nt = 0; nt < 8; nt++)
#pragma unroll
        for (int q = 0; q < 4; q++) c[nt][q] = 0.f;

    attn_issue(smb, 0, h, i0, 0, t);
    CPCOMMIT();

    for (int tl = 0; tl < NTILES; tl++) {
        if (tl < NTILES - 1) {
            attn_issue(smb, (tl + 1) & 1, h, i0, (tl + 1) * 128, t);
            CPCOMMIT();
            CPWAIT(1);
        } else {
            CPWAIT(0);
        }
        __syncthreads();

        const uint32_t bb = smb + (unsigned)(tl & 1) * BUFSZ;
        const char* bpd = dsm + (tl & 1) * BUFSZ;

        // P-fragment pipeline: fragment for slice kk computed while MMAs of kk-1 run
        PFrag f = make_frag(bpd, 0, rA0, rA1, sd0, sd1, l3, z0, z1);
#pragma unroll
        for (int kk = 0; kk < 8; kk++) {
            PFrag fn;
            if (kk < 7) fn = make_frag(bpd, kk + 1, rA0, rA1, sd0, sd1, l3, z0, z1);

            const unsigned rowoff = (unsigned)(kk * 16 + l15) * 128u;
#pragma unroll
            for (int np = 0; np < 4; np++) {
                const unsigned chn =
                    (((unsigned)(np * 2 + (lane >> 4)) ^ (unsigned)l7) << 4);
                const uint32_t ahx = bb + rowoff + chn;
                uint32_t bh0, bh1, bh2, bh3, bl0, bl1, bl2, bl3;
                LDMX4T(bh0, bh1, bh2, bh3, ahx);
                LDMX4T(bl0, bl1, bl2, bl3, ahx + BLO_O);
                MMA(c[2 * np], f.a0, f.a1, f.a2, f.a3, bh0, bh1);
                MMA(c[2 * np], f.e0, f.e1, f.e2, f.e3, bh0, bh1);
                MMA(c[2 * np], f.a0, f.a1, f.a2, f.a3, bl0, bl1);
                MMA(c[2 * np + 1], f.a0, f.a1, f.a2, f.a3, bh2, bh3);
                MMA(c[2 * np + 1], f.e0, f.e1, f.e2, f.e3, bh2, bh3);
                MMA(c[2 * np + 1], f.a0, f.a1, f.a2, f.a3, bl2, bl3);
            }
            f = fn;
        }
        __syncthreads();
    }

    z0 += __shfl_xor_sync(0xffffffffu, z0, 1);
    z0 += __shfl_xor_sync(0xffffffffu, z0, 2);
    z1 += __shfl_xor_sync(0xffffffffu, z1, 1);
    z1 += __shfl_xor_sync(0xffffffffu, z1, 2);
    const float inv0 = 1.0f / z0, inv1 = 1.0f / z1;

    float* colS = (float*)(dsm + COLS_O);
    float* colQ = (float*)(dsm + COLQ_O);

    const size_t ro0 = (size_t)(i0 + rA0) * OD + h * 64;
    const size_t ro1 = (size_t)(i0 + rA1) * OD + h * 64;
#pragma unroll
    for (int nt = 0; nt < 8; nt++) {
        float v00 = c[nt][0] * inv0, v01 = c[nt][1] * inv0;
        float v10 = c[nt][2] * inv1, v11 = c[nt][3] * inv1;
        *(float2*)&g_hp[ro0 + nt * 8 + l3 * 2] = make_float2(v00, v01);
        *(float2*)&g_hp[ro1 + nt * 8 + l3 * 2] = make_float2(v10, v11);
        float s0 = v00 + v10, s1 = v01 + v11;
        float q0 = v00 * v00 + v10 * v10, q1 = v01 * v01 + v11 * v11;
#pragma unroll
        for (int d = 4; d < 32; d <<= 1) {
            s0 += __shfl_xor_sync(0xffffffffu, s0, d);
            s1 += __shfl_xor_sync(0xffffffffu, s1, d);
            q0 += __shfl_xor_sync(0xffffffffu, q0, d);
            q1 += __shfl_xor_sync(0xffffffffu, q1, d);
        }
        if (lane < 4) {
            colS[w * 64 + nt * 8 + lane * 2] = s0;
            colS[w * 64 + nt * 8 + lane * 2 + 1] = s1;
            colQ[w * 64 + nt * 8 + lane * 2] = q0;
            colQ[w * 64 + nt * 8 + lane * 2 + 1] = q1;
        }
    }
    __syncthreads();
    if (t < 64) {
        float s = 0.f, q = 0.f;
#pragma unroll
        for (int ww = 0; ww < 8; ww++) {
            s += colS[ww * 64 + t];
            q += colQ[ww * 64 + t];
        }
        g_cs[it * OD + h * 64 + t] = s;
        g_cq[it * OD + h * 64 + t] = q;
    }
}

// ================= Kernel E: column stats (parallel) =================
__global__ void __launch_bounds__(1024) colstats_kernel() {
    const int w = threadIdx.x >> 5, lane = threadIdx.x & 31;
    const int col = blockIdx.x * 32 + w;
    float s = g_cs[lane * OD + col];
    float q = g_cq[lane * OD + col];
#pragma unroll
    for (int d = 16; d >= 1; d >>= 1) {
        s += __shfl_xor_sync(0xffffffffu, s, d);
        q += __shfl_xor_sync(0xffffffffu, q, d);
    }
    if (lane == 0) {
        float mean = s * (1.0f / Nn);
        float var = q * (1.0f / Nn) - mean * mean;
        g_mean[col] = mean;
        g_rstd[col] = rsqrtf(var + EPSV);
    }
}

// ================= Kernel F: layernorm + relu =================
__global__ void __launch_bounds__(256) norm_relu_kernel(const float* __restrict__ gamma,
                                                        const float* __restrict__ beta,
                                                        float* __restrict__ out) {
    const int idx4 = blockIdx.x * 256 + threadIdx.x;
    const int basei = idx4 * 4;
    const int col = basei & (OD - 1);
    float4 xv = *(const float4*)&g_hp[basei];
    float4 mn = *(const float4*)&g_mean[col];
    float4 rs = *(const float4*)&g_rstd[col];
    float4 ga = *(const float4*)&gamma[col];
    float4 be = *(const float4*)&beta[col];
    float4 o;
    o.x = fmaxf(0.f, ga.x * (xv.x - mn.x) * rs.x + be.x);
    o.y = fmaxf(0.f, ga.y * (xv.y - mn.y) * rs.y + be.y);
    o.z = fmaxf(0.f, ga.z * (xv.z - mn.z) * rs.z + be.z);
    o.w = fmaxf(0.f, ga.w * (xv.w - mn.w) * rs.w + be.w);
    *(float4*)&out[basei] = o;
}

// ================= launch =================
extern "C" void kernel_launch(void* const* d_in, const int* in_sizes, int n_in,
                              void* d_out, int out_size) {
    const float* x     = (const float*)d_in[0];
    const int*   adj   = (const int*)d_in[1];
    const float* W     = (const float*)d_in[2];
    const float* a     = (const float*)d_in[3];
    const float* gamma = (const float*)d_in[4];
    const float* beta  = (const float*)d_in[5];
    float* out = (float*)d_out;

    static int attrs_set = 0;
    if (!attrs_set) {
        cudaFuncSetAttribute(attn_mma_kernel,
                             cudaFuncAttributeMaxDynamicSharedMemorySize, SMEM_ATTN);
        cudaFuncSetAttribute(gemm_mma_kernel,
                             cudaFuncAttributeMaxDynamicSharedMemorySize, SMEM_GEMM);
        attrs_set = 1;
    }

    __nv_bfloat16 *xhi, *xlo, *whi, *wlo;
    cudaGetSymbolAddress((void**)&xhi, g_xhi);
    cudaGetSymbolAddress((void**)&xlo, g_xlo);
    cudaGetSymbolAddress((void**)&whi, g_whi);
    cudaGetSymbolAddress((void**)&wlo, g_wlo);

    cvt_kernel<<<(Nn * IND / 4) / 256, 256>>>(x, xhi, xlo);
    cvt_kernel<<<(OD * IND / 4) / 256, 256>>>(W, whi, wlo);
    gemm_mma_kernel<<<dim3(OD / 64, Nn / 128), 256, SMEM_GEMM>>>();
    scores_kernel<<<(Nn * Hh) / 256, 256>>>(a);
    maskpack_kernel<<<Nn, 256>>>(adj);
    attn_mma_kernel<<<dim3(Hh, ITILES), 256, SMEM_ATTN>>>();
    colstats_kernel<<<OD / 32, 1024>>>();
    norm_relu_kernel<<<(Nn * OD / 4) / 256, 256>>>(gamma, beta, out);
}

// round 8
// speedup vs baseline: 5.3064x; 1.0382x over previous
#include <cuda_runtime.h>
#include <cuda_bf16.h>
#include <cstdint>

#define Nn 4096
#define IND 512
#define OD 512
#define Hh 8
#define Dd 64
#define ALPHA 0.2f
#define EPSV 1e-5f
#define LOG2E 1.4426950408889634f
#define ITILES 16
#define NTILES 32

__device__ __nv_bfloat16 g_xhi[Nn * IND], g_xlo[Nn * IND];
__device__ __nv_bfloat16 g_whi[OD * IND], g_wlo[OD * IND];
__device__ float g_Wh[Nn * OD];
__device__ __nv_bfloat16 g_Bhi[Nn * OD];   // bf16(Wh) hi, [i][o]
__device__ __nv_bfloat16 g_Blo[Nn * OD];   // residual lo, [i][o]
__device__ float g_sdL[Hh * Nn], g_ssL[Hh * Nn];   // scores * log2(e)
__device__ unsigned g_mask[Nn * (Nn / 32)];
__device__ float g_hp[Nn * OD];
__device__ float g_cs[ITILES * OD], g_cq[ITILES * OD];
__device__ float g_mean[OD], g_rstd[OD];

__device__ __forceinline__ unsigned bfpack(float hi, float lo) {
    unsigned r;
    asm("cvt.rn.bf16x2.f32 %0, %1, %2;" : "=r"(r) : "f"(hi), "f"(lo));
    return r;
}
__device__ __forceinline__ float lowf(unsigned u) { return __uint_as_float(u << 16); }
__device__ __forceinline__ float hif(unsigned u) { return __uint_as_float(u & 0xffff0000u); }
__device__ __forceinline__ float ex2f(float x) {
    float r;
    asm("ex2.approx.ftz.f32 %0, %1;" : "=f"(r) : "f"(x));
    return r;
}
__device__ __forceinline__ uint32_t smem_u32(const void* p) {
    uint32_t a;
    asm("{ .reg .u64 t; cvta.to.shared.u64 t, %1; cvt.u32.u64 %0, t; }" : "=r"(a) : "l"(p));
    return a;
}
__device__ __forceinline__ float pfun(float tL, unsigned bit) {
    float g = fmaxf(tL, ALPHA * tL);
    float p = ex2f(g);
    return bit ? p : 0.f;
}

#define MMA(cc, A0, A1, A2, A3, B0, B1)                                            \
    asm volatile("mma.sync.aligned.m16n8k16.row.col.f32.bf16.bf16.f32 "            \
                 "{%0,%1,%2,%3},{%4,%5,%6,%7},{%8,%9},{%0,%1,%2,%3};"              \
                 : "+f"(cc[0]), "+f"(cc[1]), "+f"(cc[2]), "+f"(cc[3])              \
                 : "r"(A0), "r"(A1), "r"(A2), "r"(A3), "r"(B0), "r"(B1))

#define LDMX4T(r0, r1, r2, r3, addr)                                               \
    asm volatile("ldmatrix.sync.aligned.m8n8.x4.trans.shared.b16 {%0,%1,%2,%3},[%4];" \
                 : "=r"(r0), "=r"(r1), "=r"(r2), "=r"(r3) : "r"(addr))

#define LDMX4(r0, r1, r2, r3, addr)                                                \
    asm volatile("ldmatrix.sync.aligned.m8n8.x4.shared.b16 {%0,%1,%2,%3},[%4];"    \
                 : "=r"(r0), "=r"(r1), "=r"(r2), "=r"(r3) : "r"(addr))

#define CPA16(dst, src)                                                            \
    asm volatile("cp.async.cg.shared.global [%0], [%1], 16;" :: "r"(dst), "l"(src) : "memory")
#define CPCOMMIT() asm volatile("cp.async.commit_group;" ::: "memory")
#define CPWAIT(N) asm volatile("cp.async.wait_group %0;" :: "n"(N) : "memory")

// ================= Kernel P: fp32 -> bf16 hi/lo convert =================
__global__ void __launch_bounds__(256) cvt_kernel(const float* __restrict__ src,
                                                  __nv_bfloat16* __restrict__ hi,
                                                  __nv_bfloat16* __restrict__ lo) {
    const int i4 = (blockIdx.x * 256 + threadIdx.x) * 4;
    float4 v = *(const float4*)&src[i4];
    unsigned h01 = bfpack(v.y, v.x), h23 = bfpack(v.w, v.z);
    unsigned l01 = bfpack(v.y - hif(h01), v.x - lowf(h01));
    unsigned l23 = bfpack(v.w - hif(h23), v.z - lowf(h23));
    *(uint2*)&hi[i4] = make_uint2(h01, h23);
    *(uint2*)&lo[i4] = make_uint2(l01, l23);
}

// ================= Kernel A: Wh = x @ W^T via HMMA, double-buffered =================
#define GXHI 0
#define GXLO 16384
#define GWHI 32768
#define GWLO 40960
#define GBUF 49152
#define SMEM_GEMM (2 * GBUF)

__device__ __forceinline__ void gemm_issue(uint32_t smb, int buf, int i0, int o0, int k0, int t) {
    const uint32_t bb = smb + (unsigned)buf * GBUF;
#pragma unroll
    for (int q = 0; q < 4; q++) {
        int idx = t + q * 256;
        int i = idx >> 3, cc = idx & 7;
        unsigned so = (unsigned)i * 128u + (unsigned)((cc ^ (i & 7)) << 4);
        const size_t gof = (size_t)(i0 + i) * IND + k0 + cc * 8;
        CPA16(bb + GXHI + so, &g_xhi[gof]);
        CPA16(bb + GXLO + so, &g_xlo[gof]);
    }
#pragma unroll
    for (int q = 0; q < 2; q++) {
        int idx = t + q * 256;
        int o = idx >> 3, cc = idx & 7;
        unsigned so = (unsigned)o * 128u + (unsigned)((cc ^ (o & 7)) << 4);
        const size_t gof = (size_t)(o0 + o) * IND + k0 + cc * 8;
        CPA16(bb + GWHI + so, &g_whi[gof]);
        CPA16(bb + GWLO + so, &g_wlo[gof]);
    }
}

__global__ void __launch_bounds__(256, 2) gemm_mma_kernel() {
    extern __shared__ char dsm[];
    const uint32_t smb = smem_u32(dsm);
    const int o0 = blockIdx.x * 64, i0 = blockIdx.y * 128;
    const int t = threadIdx.x, w = t >> 5, lane = t & 31;
    const int l3 = lane & 3, l7 = lane & 7, l15 = lane & 15;

    float c[8][4];
#pragma unroll
    for (int nt = 0; nt < 8; nt++)
#pragma unroll
        for (int q = 0; q < 4; q++) c[nt][q] = 0.f;

    gemm_issue(smb, 0, i0, o0, 0, t);
    CPCOMMIT();

    for (int ch = 0; ch < 8; ch++) {
        if (ch < 7) {
            gemm_issue(smb, (ch + 1) & 1, i0, o0, (ch + 1) * 64, t);
            CPCOMMIT();
            CPWAIT(1);
        } else {
            CPWAIT(0);
        }
        __syncthreads();
        const uint32_t bb = smb + (unsigned)(ch & 1) * GBUF;

#pragma unroll
        for (int ks = 0; ks < 4; ks++) {
            uint32_t arow = bb + GXHI + (unsigned)(w * 16 + l15) * 128u +
                            (((unsigned)(2 * ks + (lane >> 4)) ^ (unsigned)l7) << 4);
            uint32_t ah0, ah1, ah2, ah3, al0, al1, al2, al3;
            LDMX4(ah0, ah1, ah2, ah3, arow);
            LDMX4(al0, al1, al2, al3, arow + 16384);
#pragma unroll
            for (int np = 0; np < 4; np++) {
                uint32_t brow = bb + GWHI +
                                (unsigned)(np * 16 + (lane >> 4) * 8 + l7) * 128u +
                                (((unsigned)(2 * ks + ((lane >> 3) & 1)) ^ (unsigned)l7) << 4);
                uint32_t bh0, bh1, bh2, bh3, bl0, bl1, bl2, bl3;
                LDMX4(bh0, bh1, bh2, bh3, brow);
                LDMX4(bl0, bl1, bl2, bl3, brow + 8192);
                MMA(c[2 * np], ah0, ah1, ah2, ah3, bh0, bh1);
                MMA(c[2 * np], al0, al1, al2, al3, bh0, bh1);
                MMA(c[2 * np], ah0, ah1, ah2, ah3, bl0, bl1);
                MMA(c[2 * np + 1], ah0, ah1, ah2, ah3, bh2, bh3);
                MMA(c[2 * np + 1], al0, al1, al2, al3, bh2, bh3);
                MMA(c[2 * np + 1], ah0, ah1, ah2, ah3, bl2, bl3);
            }
        }
        __syncthreads();
    }

    const int rA0 = w * 16 + (lane >> 2), rA1 = rA0 + 8;
#pragma unroll
    for (int nt = 0; nt < 8; nt++) {
        const int col = o0 + nt * 8 + l3 * 2;
        const size_t f0 = (size_t)(i0 + rA0) * OD + col;
        const size_t f1 = (size_t)(i0 + rA1) * OD + col;
        float v00 = c[nt][0], v01 = c[nt][1], v10 = c[nt][2], v11 = c[nt][3];
        *(float2*)&g_Wh[f0] = make_float2(v00, v01);
        *(float2*)&g_Wh[f1] = make_float2(v10, v11);
        unsigned h0 = bfpack(v01, v00), h1 = bfpack(v11, v10);
        *(unsigned*)&g_Bhi[f0] = h0;
        *(unsigned*)&g_Bhi[f1] = h1;
        *(unsigned*)&g_Blo[f0] = bfpack(v01 - hif(h0), v00 - lowf(h0));
        *(unsigned*)&g_Blo[f1] = bfpack(v11 - hif(h1), v10 - lowf(h1));
    }
}

// ================= Kernel B: adj -> bitmask =================
__global__ void __launch_bounds__(256) maskpack_kernel(const int* __restrict__ adj) {
    const int row = blockIdx.x;
    const int w = threadIdx.x >> 5, lane = threadIdx.x & 31;
    const int* arow = adj + (size_t)row * Nn;
#pragma unroll
    for (int k = 0; k < 16; k++) {
        int word = w * 16 + k;
        unsigned bal = __ballot_sync(0xffffffffu, arow[word * 32 + lane] > 0);
        if (lane == 0) g_mask[row * 128 + word] = bal;
    }
}

// ================= Kernel C: scores, warp-per-node =================
__global__ void __launch_bounds__(256) scores_kernel(const float* __restrict__ a) {
    const int w = threadIdx.x >> 5, lane = threadIdx.x & 31;
    const int j = blockIdx.x * 8 + w;
    const int h = lane >> 2, q = lane & 3;
    const float* wrow = &g_Wh[(size_t)j * OD + h * 64 + q * 16];
    float ss = 0.f, sd = 0.f;
#pragma unroll
    for (int d4 = 0; d4 < 4; d4++) {
        float4 wv = ((const float4*)wrow)[d4];
        float4 as = *(const float4*)&a[q * 16 + d4 * 4];
        float4 ad = *(const float4*)&a[64 + q * 16 + d4 * 4];
        ss += wv.x * as.x + wv.y * as.y + wv.z * as.z + wv.w * as.w;
        sd += wv.x * ad.x + wv.y * ad.y + wv.z * ad.z + wv.w * ad.w;
    }
    ss += __shfl_xor_sync(0xffffffffu, ss, 1);
    ss += __shfl_xor_sync(0xffffffffu, ss, 2);
    sd += __shfl_xor_sync(0xffffffffu, sd, 1);
    sd += __shfl_xor_sync(0xffffffffu, sd, 2);
    if (q == 0) {
        g_ssL[h * Nn + j] = ss * LOG2E;
        g_sdL[h * Nn + j] = sd * LOG2E;
    }
}

// ================= Kernel D: HMMA attention, 32 rows/warp, 1 CTA/SM =================
#define BLO_O 16384
#define MSK_O 32768
#define SSL_O 36864
#define BUFSZ 38912
#define COLS_O 77824
#define COLQ_O 79872
#define SMEM_ATTN 81920

struct PFrag {
    unsigned a0, a1, a2, a3, e0, e1, e2, e3;
};

__device__ __forceinline__ PFrag make_frag(const char* bpd, int kk, int r0, int r1,
                                           float sd0, float sd1, int l3,
                                           float& z0, float& z1) {
    const int jc = kk * 16 + l3 * 2;
    const float2 sA = *(const float2*)(bpd + SSL_O + jc * 4);
    const float2 sB = *(const float2*)(bpd + SSL_O + (jc + 8) * 4);
    const unsigned sh = (kk & 1) * 16 + l3 * 2;
    const unsigned mw0 = (*(const unsigned*)(bpd + MSK_O + r0 * 16 + ((kk >> 1) << 2))) >> sh;
    const unsigned mw1 = (*(const unsigned*)(bpd + MSK_O + r1 * 16 + ((kk >> 1) << 2))) >> sh;

    float p00 = pfun(sd0 + sA.x, mw0 & 1u);
    float p01 = pfun(sd0 + sA.y, mw0 & 2u);
    float p08 = pfun(sd0 + sB.x, (mw0 >> 8) & 1u);
    float p09 = pfun(sd0 + sB.y, (mw0 >> 8) & 2u);
    float p10 = pfun(sd1 + sA.x, mw1 & 1u);
    float p11 = pfun(sd1 + sA.y, mw1 & 2u);
    float p18 = pfun(sd1 + sB.x, (mw1 >> 8) & 1u);
    float p19 = pfun(sd1 + sB.y, (mw1 >> 8) & 2u);
    z0 += (p00 + p01) + (p08 + p09);
    z1 += (p10 + p11) + (p18 + p19);

    PFrag f;
    f.a0 = bfpack(p01, p00);
    f.a1 = bfpack(p11, p10);
    f.a2 = bfpack(p09, p08);
    f.a3 = bfpack(p19, p18);
    f.e0 = bfpack(p01 - hif(f.a0), p00 - lowf(f.a0));
    f.e1 = bfpack(p11 - hif(f.a1), p10 - lowf(f.a1));
    f.e2 = bfpack(p09 - hif(f.a2), p08 - lowf(f.a2));
    f.e3 = bfpack(p19 - hif(f.a3), p18 - lowf(f.a3));
    return f;
}

__device__ __forceinline__ void attn_issue(uint32_t smb, int b, int h, int i0, int j0, int t) {
    const uint32_t bb = smb + (unsigned)b * BUFSZ;
#pragma unroll
    for (int q = 0; q < 4; q++) {
        int idx = t + q * 256;
        int j = idx >> 3, cc = idx & 7;
        unsigned so = (unsigned)j * 128u + (unsigned)((cc ^ (j & 7)) << 4);
        const size_t gof = (size_t)(j0 + j) * OD + h * 64 + cc * 8;
        CPA16(bb + so, &g_Bhi[gof]);
        CPA16(bb + BLO_O + so, &g_Blo[gof]);
    }
    CPA16(bb + MSK_O + t * 16, &g_mask[(size_t)(i0 + t) * 128 + (j0 >> 5)]);
    if (t < 32) CPA16(bb + SSL_O + t * 16, &g_ssL[h * Nn + j0 + t * 4]);
}

__global__ void __launch_bounds__(256, 1) attn_mma_kernel() {
    extern __shared__ char dsm[];
    const uint32_t smb = smem_u32(dsm);

    const int h = blockIdx.x, it = blockIdx.y, i0 = it * 256;
    const int t = threadIdx.x, w = t >> 5, lane = t & 31;
    const int l3 = lane & 3, l7 = lane & 7, l15 = lane & 15;
    const int rB = w * 32 + (lane >> 2);     // rows rB, rB+8, rB+16, rB+24
    const float sd0 = g_sdL[h * Nn + i0 + rB];
    const float sd1 = g_sdL[h * Nn + i0 + rB + 8];
    const float sd2 = g_sdL[h * Nn + i0 + rB + 16];
    const float sd3 = g_sdL[h * Nn + i0 + rB + 24];

    float z0 = 0.f, z1 = 0.f, z2 = 0.f, z3 = 0.f;
    float c[2][8][4];
#pragma unroll
    for (int blk = 0; blk < 2; blk++)
#pragma unroll
        for (int nt = 0; nt < 8; nt++)
#pragma unroll
            for (int q = 0; q < 4; q++) c[blk][nt][q] = 0.f;

    attn_issue(smb, 0, h, i0, 0, t);
    CPCOMMIT();

    for (int tl = 0; tl < NTILES; tl++) {
        if (tl < NTILES - 1) {
            attn_issue(smb, (tl + 1) & 1, h, i0, (tl + 1) * 128, t);
            CPCOMMIT();
            CPWAIT(1);
        } else {
            CPWAIT(0);
        }
        __syncthreads();

        const uint32_t bb = smb + (unsigned)(tl & 1) * BUFSZ;
        const char* bpd = dsm + (tl & 1) * BUFSZ;

#pragma unroll
        for (int kk = 0; kk < 8; kk++) {
            PFrag f0 = make_frag(bpd, kk, rB, rB + 8, sd0, sd1, l3, z0, z1);
            PFrag f1 = make_frag(bpd, kk, rB + 16, rB + 24, sd2, sd3, l3, z2, z3);

            const unsigned rowoff = (unsigned)(kk * 16 + l15) * 128u;
#pragma unroll
            for (int np = 0; np < 4; np++) {
                const unsigned chn =
                    (((unsigned)(np * 2 + (lane >> 4)) ^ (unsigned)l7) << 4);
                const uint32_t ahx = bb + rowoff + chn;
                uint32_t bh0, bh1, bh2, bh3, bl0, bl1, bl2, bl3;
                LDMX4T(bh0, bh1, bh2, bh3, ahx);
                LDMX4T(bl0, bl1, bl2, bl3, ahx + BLO_O);
                MMA(c[0][2 * np], f0.a0, f0.a1, f0.a2, f0.a3, bh0, bh1);
                MMA(c[0][2 * np], f0.e0, f0.e1, f0.e2, f0.e3, bh0, bh1);
                MMA(c[0][2 * np], f0.a0, f0.a1, f0.a2, f0.a3, bl0, bl1);
                MMA(c[1][2 * np], f1.a0, f1.a1, f1.a2, f1.a3, bh0, bh1);
                MMA(c[1][2 * np], f1.e0, f1.e1, f1.e2, f1.e3, bh0, bh1);
                MMA(c[1][2 * np], f1.a0, f1.a1, f1.a2, f1.a3, bl0, bl1);
                MMA(c[0][2 * np + 1], f0.a0, f0.a1, f0.a2, f0.a3, bh2, bh3);
                MMA(c[0][2 * np + 1], f0.e0, f0.e1, f0.e2, f0.e3, bh2, bh3);
                MMA(c[0][2 * np + 1], f0.a0, f0.a1, f0.a2, f0.a3, bl2, bl3);
                MMA(c[1][2 * np + 1], f1.a0, f1.a1, f1.a2, f1.a3, bh2, bh3);
                MMA(c[1][2 * np + 1], f1.e0, f1.e1, f1.e2, f1.e3, bh2, bh3);
                MMA(c[1][2 * np + 1], f1.a0, f1.a1, f1.a2, f1.a3, bl2, bl3);
            }
        }
        __syncthreads();
    }

#pragma unroll
    for (int d = 1; d <= 2; d <<= 1) {
        z0 += __shfl_xor_sync(0xffffffffu, z0, d);
        z1 += __shfl_xor_sync(0xffffffffu, z1, d);
        z2 += __shfl_xor_sync(0xffffffffu, z2, d);
        z3 += __shfl_xor_sync(0xffffffffu, z3, d);
    }
    const float inv[4] = {1.0f / z0, 1.0f / z1, 1.0f / z2, 1.0f / z3};

    float* colS = (float*)(dsm + COLS_O);
    float* colQ = (float*)(dsm + COLQ_O);

#pragma unroll
    for (int nt = 0; nt < 8; nt++) {
        float vv[4][2];
#pragma unroll
        for (int blk = 0; blk < 2; blk++) {
#pragma unroll
            for (int half = 0; half < 2; half++) {
                const int ri = blk * 2 + half;
                float va = c[blk][nt][2 * half] * inv[ri];
                float vb = c[blk][nt][2 * half + 1] * inv[ri];
                vv[ri][0] = va;
                vv[ri][1] = vb;
                const int row = rB + blk * 16 + half * 8;
                *(float2*)&g_hp[(size_t)(i0 + row) * OD + h * 64 + nt * 8 + l3 * 2] =
                    make_float2(va, vb);
            }
        }
        float s0 = vv[0][0] + vv[1][0] + vv[2][0] + vv[3][0];
        float s1 = vv[0][1] + vv[1][1] + vv[2][1] + vv[3][1];
        float q0 = vv[0][0] * vv[0][0] + vv[1][0] * vv[1][0] + vv[2][0] * vv[2][0] +
                   vv[3][0] * vv[3][0];
        float q1 = vv[0][1] * vv[0][1] + vv[1][1] * vv[1][1] + vv[2][1] * vv[2][1] +
                   vv[3][1] * vv[3][1];
#pragma unroll
        for (int d = 4; d < 32; d <<= 1) {
            s0 += __shfl_xor_sync(0xffffffffu, s0, d);
            s1 += __shfl_xor_sync(0xffffffffu, s1, d);
            q0 += __shfl_xor_sync(0xffffffffu, q0, d);
            q1 += __shfl_xor_sync(0xffffffffu, q1, d);
        }
        if (lane < 4) {
            colS[w * 64 + nt * 8 + lane * 2] = s0;
            colS[w * 64 + nt * 8 + lane * 2 + 1] = s1;
            colQ[w * 64 + nt * 8 + lane * 2] = q0;
            colQ[w * 64 + nt * 8 + lane * 2 + 1] = q1;
        }
    }
    __syncthreads();
    if (t < 64) {
        float s = 0.f, q = 0.f;
#pragma unroll
        for (int ww = 0; ww < 8; ww++) {
            s += colS[ww * 64 + t];
            q += colQ[ww * 64 + t];
        }
        g_cs[it * OD + h * 64 + t] = s;
        g_cq[it * OD + h * 64 + t] = q;
    }
}

// ================= Kernel E: column stats =================
__global__ void __launch_bounds__(1024) colstats_kernel() {
    const int w = threadIdx.x >> 5, lane = threadIdx.x & 31;
    const int col = blockIdx.x * 32 + w;
    float s = (lane < ITILES) ? g_cs[lane * OD + col] : 0.f;
    float q = (lane < ITILES) ? g_cq[lane * OD + col] : 0.f;
#pragma unroll
    for (int d = 16; d >= 1; d >>= 1) {
        s += __shfl_xor_sync(0xffffffffu, s, d);
        q += __shfl_xor_sync(0xffffffffu, q, d);
    }
    if (lane == 0) {
        float mean = s * (1.0f / Nn);
        float var = q * (1.0f / Nn) - mean * mean;
        g_mean[col] = mean;
        g_rstd[col] = rsqrtf(var + EPSV);
    }
}

// ================= Kernel F: layernorm + relu =================
__global__ void __launch_bounds__(256) norm_relu_kernel(const float* __restrict__ gamma,
                                                        const float* __restrict__ beta,
                                                        float* __restrict__ out) {
    const int idx4 = blockIdx.x * 256 + threadIdx.x;
    const int basei = idx4 * 4;
    const int col = basei & (OD - 1);
    float4 xv = *(const float4*)&g_hp[basei];
    float4 mn = *(const float4*)&g_mean[col];
    float4 rs = *(const float4*)&g_rstd[col];
    float4 ga = *(const float4*)&gamma[col];
    float4 be = *(const float4*)&beta[col];
    float4 o;
    o.x = fmaxf(0.f, ga.x * (xv.x - mn.x) * rs.x + be.x);
    o.y = fmaxf(0.f, ga.y * (xv.y - mn.y) * rs.y + be.y);
    o.z = fmaxf(0.f, ga.z * (xv.z - mn.z) * rs.z + be.z);
    o.w = fmaxf(0.f, ga.w * (xv.w - mn.w) * rs.w + be.w);
    *(float4*)&out[basei] = o;
}

// ================= launch =================
extern "C" void kernel_launch(void* const* d_in, const int* in_sizes, int n_in,
                              void* d_out, int out_size) {
    const float* x     = (const float*)d_in[0];
    const int*   adj   = (const int*)d_in[1];
    const float* W     = (const float*)d_in[2];
    const float* a     = (const float*)d_in[3];
    const float* gamma = (const float*)d_in[4];
    const float* beta  = (const float*)d_in[5];
    float* out = (float*)d_out;

    static int attrs_set = 0;
    if (!attrs_set) {
        cudaFuncSetAttribute(attn_mma_kernel,
                             cudaFuncAttributeMaxDynamicSharedMemorySize, SMEM_ATTN);
        cudaFuncSetAttribute(gemm_mma_kernel,
                             cudaFuncAttributeMaxDynamicSharedMemorySize, SMEM_GEMM);
        attrs_set = 1;
    }

    __nv_bfloat16 *xhi, *xlo, *whi, *wlo;
    cudaGetSymbolAddress((void**)&xhi, g_xhi);
    cudaGetSymbolAddress((void**)&xlo, g_xlo);
    cudaGetSymbolAddress((void**)&whi, g_whi);
    cudaGetSymbolAddress((void**)&wlo, g_wlo);

    cvt_kernel<<<(Nn * IND / 4) / 256, 256>>>(x, xhi, xlo);
    cvt_kernel<<<(OD * IND / 4) / 256, 256>>>(W, whi, wlo);
    gemm_mma_kernel<<<dim3(OD / 64, Nn / 128), 256, SMEM_GEMM>>>();
    scores_kernel<<<Nn / 8, 256>>>(a);
    maskpack_kernel<<<Nn, 256>>>(adj);
    attn_mma_kernel<<<dim3(Hh, ITILES), 256, SMEM_ATTN>>>();
    colstats_kernel<<<OD / 32, 1024>>>();
    norm_relu_kernel<<<(Nn * OD / 4) / 256, 256>>>(gamma, beta, out);
}

// round 10
// speedup vs baseline: 6.5124x; 1.2273x over previous
#include <cuda_runtime.h>
#include <cuda_bf16.h>
#include <cuda_fp16.h>
#include <cstdint>

#define Nn 4096
#define IND 512
#define OD 512
#define Hh 8
#define Dd 64
#define ALPHA 0.2f
#define EPSV 1e-5f
#define LOG2E 1.4426950408889634f
#define ITILES 16
#define NTILES 32

__device__ __nv_bfloat16 g_xhi[Nn * IND], g_xlo[Nn * IND];
__device__ __nv_bfloat16 g_whi[OD * IND], g_wlo[OD * IND];
__device__ float g_Wh[Nn * OD];
__device__ __half g_Bf16[Nn * OD];                 // fp16(Wh), [i][o]
__device__ float g_sdL[Hh * Nn], g_ssL[Hh * Nn];   // scores * log2(e)
__device__ unsigned g_mask[Nn * (Nn / 32)];
__device__ float g_hp[Nn * OD];
__device__ float g_cs[ITILES * OD], g_cq[ITILES * OD];
__device__ float g_mean[OD], g_rstd[OD];

__device__ __forceinline__ unsigned bfpack(float hi, float lo) {
    unsigned r;
    asm("cvt.rn.bf16x2.f32 %0, %1, %2;" : "=r"(r) : "f"(hi), "f"(lo));
    return r;
}
__device__ __forceinline__ float lowf(unsigned u) { return __uint_as_float(u << 16); }
__device__ __forceinline__ float hif(unsigned u) { return __uint_as_float(u & 0xffff0000u); }
__device__ __forceinline__ float ex2f(float x) {
    float r;
    asm("ex2.approx.ftz.f32 %0, %1;" : "=f"(r) : "f"(x));
    return r;
}
__device__ __forceinline__ uint32_t smem_u32(const void* p) {
    uint32_t a;
    asm("{ .reg .u64 t; cvta.to.shared.u64 t, %1; cvt.u32.u64 %0, t; }" : "=r"(a) : "l"(p));
    return a;
}
__device__ __forceinline__ float pfun(float tL, unsigned bit) {
    float g = fmaxf(tL, ALPHA * tL);
    float p = ex2f(g);
    return bit ? p : 0.f;
}
// pack (lo,hi) to f16x2; return residuals
__device__ __forceinline__ unsigned hpack2(float vlo, float vhi, float& rlo, float& rhi) {
    __half2 h = __floats2half2_rn(vlo, vhi);
    float2 b = __half22float2(h);
    rlo = vlo - b.x;
    rhi = vhi - b.y;
    return reinterpret_cast<unsigned&>(h);
}
__device__ __forceinline__ unsigned hpack2n(float vlo, float vhi) {
    __half2 h = __floats2half2_rn(vlo, vhi);
    return reinterpret_cast<unsigned&>(h);
}

#define MMA(cc, A0, A1, A2, A3, B0, B1)                                            \
    asm volatile("mma.sync.aligned.m16n8k16.row.col.f32.bf16.bf16.f32 "            \
                 "{%0,%1,%2,%3},{%4,%5,%6,%7},{%8,%9},{%0,%1,%2,%3};"              \
                 : "+f"(cc[0]), "+f"(cc[1]), "+f"(cc[2]), "+f"(cc[3])              \
                 : "r"(A0), "r"(A1), "r"(A2), "r"(A3), "r"(B0), "r"(B1))

#define MMA16(cc, A0, A1, A2, A3, B0, B1)                                          \
    asm volatile("mma.sync.aligned.m16n8k16.row.col.f32.f16.f16.f32 "              \
                 "{%0,%1,%2,%3},{%4,%5,%6,%7},{%8,%9},{%0,%1,%2,%3};"              \
                 : "+f"(cc[0]), "+f"(cc[1]), "+f"(cc[2]), "+f"(cc[3])              \
                 : "r"(A0), "r"(A1), "r"(A2), "r"(A3), "r"(B0), "r"(B1))

#define LDMX4T(r0, r1, r2, r3, addr)                                               \
    asm volatile("ldmatrix.sync.aligned.m8n8.x4.trans.shared.b16 {%0,%1,%2,%3},[%4];" \
                 : "=r"(r0), "=r"(r1), "=r"(r2), "=r"(r3) : "r"(addr))

#define LDMX4(r0, r1, r2, r3, addr)                                                \
    asm volatile("ldmatrix.sync.aligned.m8n8.x4.shared.b16 {%0,%1,%2,%3},[%4];"    \
                 : "=r"(r0), "=r"(r1), "=r"(r2), "=r"(r3) : "r"(addr))

#define CPA16(dst, src)                                                            \
    asm volatile("cp.async.cg.shared.global [%0], [%1], 16;" :: "r"(dst), "l"(src) : "memory")
#define CPCOMMIT() asm volatile("cp.async.commit_group;" ::: "memory")
#define CPWAIT(N) asm volatile("cp.async.wait_group %0;" :: "n"(N) : "memory")

// ================= Kernel P: fp32 -> bf16 hi/lo convert =================
__global__ void __launch_bounds__(256) cvt_kernel(const float* __restrict__ src,
                                                  __nv_bfloat16* __restrict__ hi,
                                                  __nv_bfloat16* __restrict__ lo) {
    const int i4 = (blockIdx.x * 256 + threadIdx.x) * 4;
    float4 v = *(const float4*)&src[i4];
    unsigned h01 = bfpack(v.y, v.x), h23 = bfpack(v.w, v.z);
    unsigned l01 = bfpack(v.y - hif(h01), v.x - lowf(h01));
    unsigned l23 = bfpack(v.w - hif(h23), v.z - lowf(h23));
    *(uint2*)&hi[i4] = make_uint2(h01, h23);
    *(uint2*)&lo[i4] = make_uint2(l01, l23);
}

// ================= Kernel A: Wh = x @ W^T via HMMA (bf16 3-MMA), double-buffered =================
#define GXHI 0
#define GXLO 16384
#define GWHI 32768
#define GWLO 40960
#define GBUF 49152
#define SMEM_GEMM (2 * GBUF)

__device__ __forceinline__ void gemm_issue(uint32_t smb, int buf, int i0, int o0, int k0, int t) {
    const uint32_t bb = smb + (unsigned)buf * GBUF;
#pragma unroll
    for (int q = 0; q < 4; q++) {
        int idx = t + q * 256;
        int i = idx >> 3, cc = idx & 7;
        unsigned so = (unsigned)i * 128u + (unsigned)((cc ^ (i & 7)) << 4);
        const size_t gof = (size_t)(i0 + i) * IND + k0 + cc * 8;
        CPA16(bb + GXHI + so, &g_xhi[gof]);
        CPA16(bb + GXLO + so, &g_xlo[gof]);
    }
#pragma unroll
    for (int q = 0; q < 2; q++) {
        int idx = t + q * 256;
        int o = idx >> 3, cc = idx & 7;
        unsigned so = (unsigned)o * 128u + (unsigned)((cc ^ (o & 7)) << 4);
        const size_t gof = (size_t)(o0 + o) * IND + k0 + cc * 8;
        CPA16(bb + GWHI + so, &g_whi[gof]);
        CPA16(bb + GWLO + so, &g_wlo[gof]);
    }
}

__global__ void __launch_bounds__(256, 2) gemm_mma_kernel() {
    extern __shared__ char dsm[];
    const uint32_t smb = smem_u32(dsm);
    const int o0 = blockIdx.x * 64, i0 = blockIdx.y * 128;
    const int t = threadIdx.x, w = t >> 5, lane = t & 31;
    const int l3 = lane & 3, l7 = lane & 7, l15 = lane & 15;

    float c[8][4];
#pragma unroll
    for (int nt = 0; nt < 8; nt++)
#pragma unroll
        for (int q = 0; q < 4; q++) c[nt][q] = 0.f;

    gemm_issue(smb, 0, i0, o0, 0, t);
    CPCOMMIT();

    for (int ch = 0; ch < 8; ch++) {
        if (ch < 7) {
            gemm_issue(smb, (ch + 1) & 1, i0, o0, (ch + 1) * 64, t);
            CPCOMMIT();
            CPWAIT(1);
        } else {
            CPWAIT(0);
        }
        __syncthreads();
        const uint32_t bb = smb + (unsigned)(ch & 1) * GBUF;

#pragma unroll
        for (int ks = 0; ks < 4; ks++) {
            uint32_t arow = bb + GXHI + (unsigned)(w * 16 + l15) * 128u +
                            (((unsigned)(2 * ks + (lane >> 4)) ^ (unsigned)l7) << 4);
            uint32_t ah0, ah1, ah2, ah3, al0, al1, al2, al3;
            LDMX4(ah0, ah1, ah2, ah3, arow);
            LDMX4(al0, al1, al2, al3, arow + 16384);
#pragma unroll
            for (int np = 0; np < 4; np++) {
                uint32_t brow = bb + GWHI +
                                (unsigned)(np * 16 + (lane >> 4) * 8 + l7) * 128u +
                                (((unsigned)(2 * ks + ((lane >> 3) & 1)) ^ (unsigned)l7) << 4);
                uint32_t bh0, bh1, bh2, bh3, bl0, bl1, bl2, bl3;
                LDMX4(bh0, bh1, bh2, bh3, brow);
                LDMX4(bl0, bl1, bl2, bl3, brow + 8192);
                MMA(c[2 * np], ah0, ah1, ah2, ah3, bh0, bh1);
                MMA(c[2 * np], al0, al1, al2, al3, bh0, bh1);
                MMA(c[2 * np], ah0, ah1, ah2, ah3, bl0, bl1);
                MMA(c[2 * np + 1], ah0, ah1, ah2, ah3, bh2, bh3);
                MMA(c[2 * np + 1], al0, al1, al2, al3, bh2, bh3);
                MMA(c[2 * np + 1], ah0, ah1, ah2, ah3, bl2, bl3);
            }
        }
        __syncthreads();
    }

    const int rA0 = w * 16 + (lane >> 2), rA1 = rA0 + 8;
#pragma unroll
    for (int nt = 0; nt < 8; nt++) {
        const int col = o0 + nt * 8 + l3 * 2;
        const size_t f0 = (size_t)(i0 + rA0) * OD + col;
        const size_t f1 = (size_t)(i0 + rA1) * OD + col;
        float v00 = c[nt][0], v01 = c[nt][1], v10 = c[nt][2], v11 = c[nt][3];
        *(float2*)&g_Wh[f0] = make_float2(v00, v01);
        *(float2*)&g_Wh[f1] = make_float2(v10, v11);
        *(unsigned*)&g_Bf16[f0] = hpack2n(v00, v01);
        *(unsigned*)&g_Bf16[f1] = hpack2n(v10, v11);
    }
}

// ================= Kernel B: adj -> bitmask =================
__global__ void __launch_bounds__(256) maskpack_kernel(const int* __restrict__ adj) {
    const int row = blockIdx.x;
    const int w = threadIdx.x >> 5, lane = threadIdx.x & 31;
    const int* arow = adj + (size_t)row * Nn;
#pragma unroll
    for (int k = 0; k < 16; k++) {
        int word = w * 16 + k;
        unsigned bal = __ballot_sync(0xffffffffu, arow[word * 32 + lane] > 0);
        if (lane == 0) g_mask[row * 128 + word] = bal;
    }
}

// ================= Kernel C: scores, warp-per-node =================
__global__ void __launch_bounds__(256) scores_kernel(const float* __restrict__ a) {
    const int w = threadIdx.x >> 5, lane = threadIdx.x & 31;
    const int j = blockIdx.x * 8 + w;
    const int h = lane >> 2, q = lane & 3;
    const float* wrow = &g_Wh[(size_t)j * OD + h * 64 + q * 16];
    float ss = 0.f, sd = 0.f;
#pragma unroll
    for (int d4 = 0; d4 < 4; d4++) {
        float4 wv = ((const float4*)wrow)[d4];
        float4 as = *(const float4*)&a[q * 16 + d4 * 4];
        float4 ad = *(const float4*)&a[64 + q * 16 + d4 * 4];
        ss += wv.x * as.x + wv.y * as.y + wv.z * as.z + wv.w * as.w;
        sd += wv.x * ad.x + wv.y * ad.y + wv.z * ad.z + wv.w * ad.w;
    }
    ss += __shfl_xor_sync(0xffffffffu, ss, 1);
    ss += __shfl_xor_sync(0xffffffffu, ss, 2);
    sd += __shfl_xor_sync(0xffffffffu, sd, 1);
    sd += __shfl_xor_sync(0xffffffffu, sd, 2);
    if (q == 0) {
        g_ssL[h * Nn + j] = ss * LOG2E;
        g_sdL[h * Nn + j] = sd * LOG2E;
    }
}

// ================= Kernel D: fp16 2-MMA attention, 32 rows/warp, 1 CTA/SM =================
#define MSK_O 16384
#define SSL_O 20480
#define BUFSZ 21504
#define COLS_O 43008
#define COLQ_O 45056
#define SMEM_ATTN 47104

struct PFrag {
    unsigned a0, a1, a2, a3, e0, e1, e2, e3;
};

__device__ __forceinline__ PFrag make_frag(const char* bpd, int kk, int r0, int r1,
                                           float sd0, float sd1, int l3,
                                           float& z0, float& z1) {
    const int jc = kk * 16 + l3 * 2;
    const float2 sA = *(const float2*)(bpd + SSL_O + jc * 4);
    const float2 sB = *(const float2*)(bpd + SSL_O + (jc + 8) * 4);
    const unsigned sh = (kk & 1) * 16 + l3 * 2;
    const unsigned mw0 = (*(const unsigned*)(bpd + MSK_O + r0 * 16 + ((kk >> 1) << 2))) >> sh;
    const unsigned mw1 = (*(const unsigned*)(bpd + MSK_O + r1 * 16 + ((kk >> 1) << 2))) >> sh;

    float p00 = pfun(sd0 + sA.x, mw0 & 1u);
    float p01 = pfun(sd0 + sA.y, mw0 & 2u);
    float p08 = pfun(sd0 + sB.x, (mw0 >> 8) & 1u);
    float p09 = pfun(sd0 + sB.y, (mw0 >> 8) & 2u);
    float p10 = pfun(sd1 + sA.x, mw1 & 1u);
    float p11 = pfun(sd1 + sA.y, mw1 & 2u);
    float p18 = pfun(sd1 + sB.x, (mw1 >> 8) & 1u);
    float p19 = pfun(sd1 + sB.y, (mw1 >> 8) & 2u);
    z0 += (p00 + p01) + (p08 + p09);
    z1 += (p10 + p11) + (p18 + p19);

    PFrag f;
    float r00, r01, r08, r09, r10, r11, r18, r19;
    f.a0 = hpack2(p00, p01, r00, r01);
    f.a1 = hpack2(p10, p11, r10, r11);
    f.a2 = hpack2(p08, p09, r08, r09);
    f.a3 = hpack2(p18, p19, r18, r19);
    f.e0 = hpack2n(r00, r01);
    f.e1 = hpack2n(r10, r11);
    f.e2 = hpack2n(r08, r09);
    f.e3 = hpack2n(r18, r19);
    return f;
}

__device__ __forceinline__ void attn_issue(uint32_t smb, int b, int h, int i0, int j0, int t) {
    const uint32_t bb = smb + (unsigned)b * BUFSZ;
#pragma unroll
    for (int q = 0; q < 4; q++) {
        int idx = t + q * 256;
        int j = idx >> 3, cc = idx & 7;
        unsigned so = (unsigned)j * 128u + (unsigned)((cc ^ (j & 7)) << 4);
        CPA16(bb + so, &g_Bf16[(size_t)(j0 + j) * OD + h * 64 + cc * 8]);
    }
    CPA16(bb + MSK_O + t * 16, &g_mask[(size_t)(i0 + t) * 128 + (j0 >> 5)]);
    if (t < 32) CPA16(bb + SSL_O + t * 16, &g_ssL[h * Nn + j0 + t * 4]);
}

__global__ void __launch_bounds__(256, 1) attn_mma_kernel() {
    extern __shared__ char dsm[];
    const uint32_t smb = smem_u32(dsm);

    const int h = blockIdx.x, it = blockIdx.y, i0 = it * 256;
    const int t = threadIdx.x, w = t >> 5, lane = t & 31;
    const int l3 = lane & 3, l7 = lane & 7, l15 = lane & 15;
    const int rB = w * 32 + (lane >> 2);
    const float sd0 = g_sdL[h * Nn + i0 + rB];
    const float sd1 = g_sdL[h * Nn + i0 + rB + 8];
    const float sd2 = g_sdL[h * Nn + i0 + rB + 16];
    const float sd3 = g_sdL[h * Nn + i0 + rB + 24];

    float z0 = 0.f, z1 = 0.f, z2 = 0.f, z3 = 0.f;
    float c[2][8][4];
#pragma unroll
    for (int blk = 0; blk < 2; blk++)
#pragma unroll
        for (int nt = 0; nt < 8; nt++)
#pragma unroll
            for (int q = 0; q < 4; q++) c[blk][nt][q] = 0.f;

    attn_issue(smb, 0, h, i0, 0, t);
    CPCOMMIT();

    for (int tl = 0; tl < NTILES; tl++) {
        if (tl < NTILES - 1) {
            attn_issue(smb, (tl + 1) & 1, h, i0, (tl + 1) * 128, t);
            CPCOMMIT();
            CPWAIT(1);
        } else {
            CPWAIT(0);
        }
        __syncthreads();

        const uint32_t bb = smb + (unsigned)(tl & 1) * BUFSZ;
        const char* bpd = dsm + (tl & 1) * BUFSZ;

#pragma unroll
        for (int kk = 0; kk < 8; kk++) {
            PFrag f0 = make_frag(bpd, kk, rB, rB + 8, sd0, sd1, l3, z0, z1);
            PFrag f1 = make_frag(bpd, kk, rB + 16, rB + 24, sd2, sd3, l3, z2, z3);

            const unsigned rowoff = (unsigned)(kk * 16 + l15) * 128u;
#pragma unroll
            for (int np = 0; np < 4; np++) {
                const unsigned chn =
                    (((unsigned)(np * 2 + (lane >> 4)) ^ (unsigned)l7) << 4);
                uint32_t bh0, bh1, bh2, bh3;
                LDMX4T(bh0, bh1, bh2, bh3, bb + rowoff + chn);
                MMA16(c[0][2 * np], f0.a0, f0.a1, f0.a2, f0.a3, bh0, bh1);
                MMA16(c[0][2 * np], f0.e0, f0.e1, f0.e2, f0.e3, bh0, bh1);
                MMA16(c[1][2 * np], f1.a0, f1.a1, f1.a2, f1.a3, bh0, bh1);
                MMA16(c[1][2 * np], f1.e0, f1.e1, f1.e2, f1.e3, bh0, bh1);
                MMA16(c[0][2 * np + 1], f0.a0, f0.a1, f0.a2, f0.a3, bh2, bh3);
                MMA16(c[0][2 * np + 1], f0.e0, f0.e1, f0.e2, f0.e3, bh2, bh3);
                MMA16(c[1][2 * np + 1], f1.a0, f1.a1, f1.a2, f1.a3, bh2, bh3);
                MMA16(c[1][2 * np + 1], f1.e0, f1.e1, f1.e2, f1.e3, bh2, bh3);
            }
        }
        __syncthreads();
    }

#pragma unroll
    for (int d = 1; d <= 2; d <<= 1) {
        z0 += __shfl_xor_sync(0xffffffffu, z0, d);
        z1 += __shfl_xor_sync(0xffffffffu, z1, d);
        z2 += __shfl_xor_sync(0xffffffffu, z2, d);
        z3 += __shfl_xor_sync(0xffffffffu, z3, d);
    }
    const float inv[4] = {1.0f / z0, 1.0f / z1, 1.0f / z2, 1.0f / z3};

    float* colS = (float*)(dsm + COLS_O);
    float* colQ = (float*)(dsm + COLQ_O);

#pragma unroll
    for (int nt = 0; nt < 8; nt++) {
        float vv[4][2];
#pragma unroll
        for (int blk = 0; blk < 2; blk++) {
#pragma unroll
            for (int half = 0; half < 2; half++) {
                const int ri = blk * 2 + half;
                float va = c[blk][nt][2 * half] * inv[ri];
                float vb = c[blk][nt][2 * half + 1] * inv[ri];
                vv[ri][0] = va;
                vv[ri][1] = vb;
                const int row = rB + blk * 16 + half * 8;
                *(float2*)&g_hp[(size_t)(i0 + row) * OD + h * 64 + nt * 8 + l3 * 2] =
                    make_float2(va, vb);
            }
        }
        float s0 = vv[0][0] + vv[1][0] + vv[2][0] + vv[3][0];
        float s1 = vv[0][1] + vv[1][1] + vv[2][1] + vv[3][1];
        float q0 = vv[0][0] * vv[0][0] + vv[1][0] * vv[1][0] + vv[2][0] * vv[2][0] +
                   vv[3][0] * vv[3][0];
        float q1 = vv[0][1] * vv[0][1] + vv[1][1] * vv[1][1] + vv[2][1] * vv[2][1] +
                   vv[3][1] * vv[3][1];
#pragma unroll
        for (int d = 4; d < 32; d <<= 1) {
            s0 += __shfl_xor_sync(0xffffffffu, s0, d);
            s1 += __shfl_xor_sync(0xffffffffu, s1, d);
            q0 += __shfl_xor_sync(0xffffffffu, q0, d);
            q1 += __shfl_xor_sync(0xffffffffu, q1, d);
        }
        if (lane < 4) {
            colS[w * 64 + nt * 8 + lane * 2] = s0;
            colS[w * 64 + nt * 8 + lane * 2 + 1] = s1;
            colQ[w * 64 + nt * 8 + lane * 2] = q0;
            colQ[w * 64 + nt * 8 + lane * 2 + 1] = q1;
        }
    }
    __syncthreads();
    if (t < 64) {
        float s = 0.f, q = 0.f;
#pragma unroll
        for (int ww = 0; ww < 8; ww++) {
            s += colS[ww * 64 + t];
            q += colQ[ww * 64 + t];
        }
        g_cs[it * OD + h * 64 + t] = s;
        g_cq[it * OD + h * 64 + t] = q;
    }
}

// ================= Kernel E: column stats =================
__global__ void __launch_bounds__(1024) colstats_kernel() {
    const int w = threadIdx.x >> 5, lane = threadIdx.x & 31;
    const int col = blockIdx.x * 32 + w;
    float s = (lane < ITILES) ? g_cs[lane * OD + col] : 0.f;
    float q = (lane < ITILES) ? g_cq[lane * OD + col] : 0.f;
#pragma unroll
    for (int d = 16; d >= 1; d >>= 1) {
        s += __shfl_xor_sync(0xffffffffu, s, d);
        q += __shfl_xor_sync(0xffffffffu, q, d);
    }
    if (lane == 0) {
        float mean = s * (1.0f / Nn);
        float var = q * (1.0f / Nn) - mean * mean;
        g_mean[col] = mean;
        g_rstd[col] = rsqrtf(var + EPSV);
    }
}

// ================= Kernel F: layernorm + relu (2 float4 / thread) =================
__global__ void __launch_bounds__(256) norm_relu_kernel(const float* __restrict__ gamma,
                                                        const float* __restrict__ beta,
                                                        float* __restrict__ out) {
    const int base8 = (blockIdx.x * 256 + threadIdx.x) * 8;
#pragma unroll
    for (int half = 0; half < 2; half++) {
        const int basei = base8 + half * 4;
        const int col = basei & (OD - 1);
        float4 xv = *(const float4*)&g_hp[basei];
        float4 mn = *(const float4*)&g_mean[col];
        float4 rs = *(const float4*)&g_rstd[col];
        float4 ga = *(const float4*)&gamma[col];
        float4 be = *(const float4*)&beta[col];
        float4 o;
        o.x = fmaxf(0.f, ga.x * (xv.x - mn.x) * rs.x + be.x);
        o.y = fmaxf(0.f, ga.y * (xv.y - mn.y) * rs.y + be.y);
        o.z = fmaxf(0.f, ga.z * (xv.z - mn.z) * rs.z + be.z);
        o.w = fmaxf(0.f, ga.w * (xv.w - mn.w) * rs.w + be.w);
        *(float4*)&out[basei] = o;
    }
}

// ================= launch =================
extern "C" void kernel_launch(void* const* d_in, const int* in_sizes, int n_in,
                              void* d_out, int out_size) {
    const float* x     = (const float*)d_in[0];
    const int*   adj   = (const int*)d_in[1];
    const float* W     = (const float*)d_in[2];
    const float* a     = (const float*)d_in[3];
    const float* gamma = (const float*)d_in[4];
    const float* beta  = (const float*)d_in[5];
    float* out = (float*)d_out;

    static int attrs_set = 0;
    if (!attrs_set) {
        cudaFuncSetAttribute(attn_mma_kernel,
                             cudaFuncAttributeMaxDynamicSharedMemorySize, SMEM_ATTN);
        cudaFuncSetAttribute(gemm_mma_kernel,
                             cudaFuncAttributeMaxDynamicSharedMemorySize, SMEM_GEMM);
        attrs_set = 1;
    }

    __nv_bfloat16 *xhi, *xlo, *whi, *wlo;
    cudaGetSymbolAddress((void**)&xhi, g_xhi);
    cudaGetSymbolAddress((void**)&xlo, g_xlo);
    cudaGetSymbolAddress((void**)&whi, g_whi);
    cudaGetSymbolAddress((void**)&wlo, g_wlo);

    cvt_kernel<<<(Nn * IND / 4) / 256, 256>>>(x, xhi, xlo);
    cvt_kernel<<<(OD * IND / 4) / 256, 256>>>(W, whi, wlo);
    gemm_mma_kernel<<<dim3(OD / 64, Nn / 128), 256, SMEM_GEMM>>>();
    scores_kernel<<<Nn / 8, 256>>>(a);
    maskpack_kernel<<<Nn, 256>>>(adj);
    attn_mma_kernel<<<dim3(Hh, ITILES), 256, SMEM_ATTN>>>();
    colstats_kernel<<<OD / 32, 1024>>>();
    norm_relu_kernel<<<(Nn * OD / 8) / 256, 256>>>(gamma, beta, out);
}

// round 13
// speedup vs baseline: 8.4182x; 1.2926x over previous
#include <cuda_runtime.h>
#include <cuda_bf16.h>
#include <cuda_fp16.h>
#include <cstdint>

#define Nn 4096
#define IND 512
#define OD 512
#define Hh 8
#define Dd 64
#define ALPHA 0.2f
#define EPSV 1e-5f
#define LOG2E 1.4426950408889634f
#define ITILES 16
#define NTILES 32

__device__ __nv_bfloat16 g_xhi[Nn * IND], g_xlo[Nn * IND];
__device__ __nv_bfloat16 g_whi[OD * IND], g_wlo[OD * IND];
__device__ float g_Wh[Nn * OD];
__device__ __half g_Bf16[Nn * OD];                 // fp16(Wh), [i][o]
__device__ float g_sdL[Hh * Nn], g_ssL[Hh * Nn];   // scores * log2(e)
__device__ unsigned g_mask[Nn * (Nn / 32)];
__device__ float g_hp[Nn * OD];
__device__ float g_cs[ITILES * OD], g_cq[ITILES * OD];
__device__ float g_mean[OD], g_rstd[OD];

__device__ __forceinline__ unsigned bfpack(float hi, float lo) {
    unsigned r;
    asm("cvt.rn.bf16x2.f32 %0, %1, %2;" : "=r"(r) : "f"(hi), "f"(lo));
    return r;
}
__device__ __forceinline__ float lowf(unsigned u) { return __uint_as_float(u << 16); }
__device__ __forceinline__ float hif(unsigned u) { return __uint_as_float(u & 0xffff0000u); }
__device__ __forceinline__ float ex2f(float x) {
    float r;
    asm("ex2.approx.ftz.f32 %0, %1;" : "=f"(r) : "f"(x));
    return r;
}
__device__ __forceinline__ uint32_t smem_u32(const void* p) {
    uint32_t a;
    asm("{ .reg .u64 t; cvta.to.shared.u64 t, %1; cvt.u32.u64 %0, t; }" : "=r"(a) : "l"(p));
    return a;
}
__device__ __forceinline__ float pfun(float tL, unsigned bit) {
    float g = fmaxf(tL, ALPHA * tL);
    float p = ex2f(g);
    return bit ? p : 0.f;
}
__device__ __forceinline__ unsigned hpack2n(float vlo, float vhi) {
    __half2 h = __floats2half2_rn(vlo, vhi);
    return reinterpret_cast<unsigned&>(h);
}

#define MMA(cc, A0, A1, A2, A3, B0, B1)                                            \
    asm volatile("mma.sync.aligned.m16n8k16.row.col.f32.bf16.bf16.f32 "            \
                 "{%0,%1,%2,%3},{%4,%5,%6,%7},{%8,%9},{%0,%1,%2,%3};"              \
                 : "+f"(cc[0]), "+f"(cc[1]), "+f"(cc[2]), "+f"(cc[3])              \
                 : "r"(A0), "r"(A1), "r"(A2), "r"(A3), "r"(B0), "r"(B1))

#define MMA16(cc, A0, A1, A2, A3, B0, B1)                                          \
    asm volatile("mma.sync.aligned.m16n8k16.row.col.f32.f16.f16.f32 "              \
                 "{%0,%1,%2,%3},{%4,%5,%6,%7},{%8,%9},{%0,%1,%2,%3};"              \
                 : "+f"(cc[0]), "+f"(cc[1]), "+f"(cc[2]), "+f"(cc[3])              \
                 : "r"(A0), "r"(A1), "r"(A2), "r"(A3), "r"(B0), "r"(B1))

#define LDMX4T(r0, r1, r2, r3, addr)                                               \
    asm volatile("ldmatrix.sync.aligned.m8n8.x4.trans.shared.b16 {%0,%1,%2,%3},[%4];" \
                 : "=r"(r0), "=r"(r1), "=r"(r2), "=r"(r3) : "r"(addr))

#define LDMX4(r0, r1, r2, r3, addr)                                                \
    asm volatile("ldmatrix.sync.aligned.m8n8.x4.shared.b16 {%0,%1,%2,%3},[%4];"    \
                 : "=r"(r0), "=r"(r1), "=r"(r2), "=r"(r3) : "r"(addr))

#define CPA16(dst, src)                                                            \
    asm volatile("cp.async.cg.shared.global [%0], [%1], 16;" :: "r"(dst), "l"(src) : "memory")
#define CPCOMMIT() asm volatile("cp.async.commit_group;" ::: "memory")
#define CPWAIT(N) asm volatile("cp.async.wait_group %0;" :: "n"(N) : "memory")

// ================= Kernel P: fp32 -> bf16 hi/lo convert =================
__global__ void __launch_bounds__(256) cvt_kernel(const float* __restrict__ src,
                                                  __nv_bfloat16* __restrict__ hi,
                                                  __nv_bfloat16* __restrict__ lo) {
    const int i4 = (blockIdx.x * 256 + threadIdx.x) * 4;
    float4 v = *(const float4*)&src[i4];
    unsigned h01 = bfpack(v.y, v.x), h23 = bfpack(v.w, v.z);
    unsigned l01 = bfpack(v.y - hif(h01), v.x - lowf(h01));
    unsigned l23 = bfpack(v.w - hif(h23), v.z - lowf(h23));
    *(uint2*)&hi[i4] = make_uint2(h01, h23);
    *(uint2*)&lo[i4] = make_uint2(l01, l23);
}

// ================= Kernel A: Wh = x @ W^T via HMMA (bf16 3-MMA), double-buffered =================
#define GXHI 0
#define GXLO 16384
#define GWHI 32768
#define GWLO 40960
#define GBUF 49152
#define SMEM_GEMM (2 * GBUF)

__device__ __forceinline__ void gemm_issue(uint32_t smb, int buf, int i0, int o0, int k0, int t) {
    const uint32_t bb = smb + (unsigned)buf * GBUF;
#pragma unroll
    for (int q = 0; q < 4; q++) {
        int idx = t + q * 256;
        int i = idx >> 3, cc = idx & 7;
        unsigned so = (unsigned)i * 128u + (unsigned)((cc ^ (i & 7)) << 4);
        const size_t gof = (size_t)(i0 + i) * IND + k0 + cc * 8;
        CPA16(bb + GXHI + so, &g_xhi[gof]);
        CPA16(bb + GXLO + so, &g_xlo[gof]);
    }
#pragma unroll
    for (int q = 0; q < 2; q++) {
        int idx = t + q * 256;
        int o = idx >> 3, cc = idx & 7;
        unsigned so = (unsigned)o * 128u + (unsigned)((cc ^ (o & 7)) << 4);
        const size_t gof = (size_t)(o0 + o) * IND + k0 + cc * 8;
        CPA16(bb + GWHI + so, &g_whi[gof]);
        CPA16(bb + GWLO + so, &g_wlo[gof]);
    }
}

__global__ void __launch_bounds__(256, 2) gemm_mma_kernel() {
    extern __shared__ char dsm[];
    const uint32_t smb = smem_u32(dsm);
    const int o0 = blockIdx.x * 64, i0 = blockIdx.y * 128;
    const int t = threadIdx.x, w = t >> 5, lane = t & 31;
    const int l3 = lane & 3, l7 = lane & 7, l15 = lane & 15;

    float c[8][4];
#pragma unroll
    for (int nt = 0; nt < 8; nt++)
#pragma unroll
        for (int q = 0; q < 4; q++) c[nt][q] = 0.f;

    gemm_issue(smb, 0, i0, o0, 0, t);
    CPCOMMIT();

    for (int ch = 0; ch < 8; ch++) {
        if (ch < 7) {
            gemm_issue(smb, (ch + 1) & 1, i0, o0, (ch + 1) * 64, t);
            CPCOMMIT();
            CPWAIT(1);
        } else {
            CPWAIT(0);
        }
        __syncthreads();
        const uint32_t bb = smb + (unsigned)(ch & 1) * GBUF;

#pragma unroll
        for (int ks = 0; ks < 4; ks++) {
            uint32_t arow = bb + GXHI + (unsigned)(w * 16 + l15) * 128u +
                            (((unsigned)(2 * ks + (lane >> 4)) ^ (unsigned)l7) << 4);
            uint32_t ah0, ah1, ah2, ah3, al0, al1, al2, al3;
            LDMX4(ah0, ah1, ah2, ah3, arow);
            LDMX4(al0, al1, al2, al3, arow + 16384);
#pragma unroll
            for (int np = 0; np < 4; np++) {
                uint32_t brow = bb + GWHI +
                                (unsigned)(np * 16 + (lane >> 4) * 8 + l7) * 128u +
                                (((unsigned)(2 * ks + ((lane >> 3) & 1)) ^ (unsigned)l7) << 4);
                uint32_t bh0, bh1, bh2, bh3, bl0, bl1, bl2, bl3;
                LDMX4(bh0, bh1, bh2, bh3, brow);
                LDMX4(bl0, bl1, bl2, bl3, brow + 8192);
                MMA(c[2 * np], ah0, ah1, ah2, ah3, bh0, bh1);
                MMA(c[2 * np], al0, al1, al2, al3, bh0, bh1);
                MMA(c[2 * np], ah0, ah1, ah2, ah3, bl0, bl1);
                MMA(c[2 * np + 1], ah0, ah1, ah2, ah3, bh2, bh3);
                MMA(c[2 * np + 1], al0, al1, al2, al3, bh2, bh3);
                MMA(c[2 * np + 1], ah0, ah1, ah2, ah3, bl2, bl3);
            }
        }
        __syncthreads();
    }

    const int rA0 = w * 16 + (lane >> 2), rA1 = rA0 + 8;
#pragma unroll
    for (int nt = 0; nt < 8; nt++) {
        const int col = o0 + nt * 8 + l3 * 2;
        const size_t f0 = (size_t)(i0 + rA0) * OD + col;
        const size_t f1 = (size_t)(i0 + rA1) * OD + col;
        float v00 = c[nt][0], v01 = c[nt][1], v10 = c[nt][2], v11 = c[nt][3];
        *(float2*)&g_Wh[f0] = make_float2(v00, v01);
        *(float2*)&g_Wh[f1] = make_float2(v10, v11);
        *(unsigned*)&g_Bf16[f0] = hpack2n(v00, v01);
        *(unsigned*)&g_Bf16[f1] = hpack2n(v10, v11);
    }
}

// ================= Kernel B: adj -> bitmask =================
__global__ void __launch_bounds__(256) maskpack_kernel(const int* __restrict__ adj) {
    const int row = blockIdx.x;
    const int w = threadIdx.x >> 5, lane = threadIdx.x & 31;
    const int* arow = adj + (size_t)row * Nn;
#pragma unroll
    for (int k = 0; k < 16; k++) {
        int word = w * 16 + k;
        unsigned bal = __ballot_sync(0xffffffffu, arow[word * 32 + lane] > 0);
        if (lane == 0) g_mask[row * 128 + word] = bal;
    }
}

// ================= Kernel C: scores, warp-per-node =================
__global__ void __launch_bounds__(256) scores_kernel(const float* __restrict__ a) {
    const int w = threadIdx.x >> 5, lane = threadIdx.x & 31;
    const int j = blockIdx.x * 8 + w;
    const int h = lane >> 2, q = lane & 3;
    const float* wrow = &g_Wh[(size_t)j * OD + h * 64 + q * 16];
    float ss = 0.f, sd = 0.f;
#pragma unroll
    for (int d4 = 0; d4 < 4; d4++) {
        float4 wv = ((const float4*)wrow)[d4];
        float4 as = *(const float4*)&a[q * 16 + d4 * 4];
        float4 ad = *(const float4*)&a[64 + q * 16 + d4 * 4];
        ss += wv.x * as.x + wv.y * as.y + wv.z * as.z + wv.w * as.w;
        sd += wv.x * ad.x + wv.y * ad.y + wv.z * ad.z + wv.w * ad.w;
    }
    ss += __shfl_xor_sync(0xffffffffu, ss, 1);
    ss += __shfl_xor_sync(0xffffffffu, ss, 2);
    sd += __shfl_xor_sync(0xffffffffu, sd, 1);
    sd += __shfl_xor_sync(0xffffffffu, sd, 2);
    if (q == 0) {
        g_ssL[h * Nn + j] = ss * LOG2E;
        g_sdL[h * Nn + j] = sd * LOG2E;
    }
}

// ================= Kernel D: fp16 1-MMA attention, 32 rows/warp, 1 CTA/SM =================
#define MSK_O 16384
#define SSL_O 20480
#define BUFSZ 21504
#define COLS_O 43008
#define COLQ_O 45056
#define SMEM_ATTN 47104

struct PFrag {
    unsigned a0, a1, a2, a3;
};

__device__ __forceinline__ PFrag make_frag(const char* bpd, int kk, int r0, int r1,
                                           float sd0, float sd1, int l3,
                                           float& z0, float& z1) {
    const int jc = kk * 16 + l3 * 2;
    const float2 sA = *(const float2*)(bpd + SSL_O + jc * 4);
    const float2 sB = *(const float2*)(bpd + SSL_O + (jc + 8) * 4);
    const unsigned sh = (kk & 1) * 16 + l3 * 2;
    const unsigned mw0 = (*(const unsigned*)(bpd + MSK_O + r0 * 16 + ((kk >> 1) << 2))) >> sh;
    const unsigned mw1 = (*(const unsigned*)(bpd + MSK_O + r1 * 16 + ((kk >> 1) << 2))) >> sh;

    float p00 = pfun(sd0 + sA.x, mw0 & 1u);
    float p01 = pfun(sd0 + sA.y, mw0 & 2u);
    float p08 = pfun(sd0 + sB.x, (mw0 >> 8) & 1u);
    float p09 = pfun(sd0 + sB.y, (mw0 >> 8) & 2u);
    float p10 = pfun(sd1 + sA.x, mw1 & 1u);
    float p11 = pfun(sd1 + sA.y, mw1 & 2u);
    float p18 = pfun(sd1 + sB.x, (mw1 >> 8) & 1u);
    float p19 = pfun(sd1 + sB.y, (mw1 >> 8) & 2u);
    z0 += (p00 + p01) + (p08 + p09);
    z1 += (p10 + p11) + (p18 + p19);

    PFrag f;
    f.a0 = hpack2n(p00, p01);
    f.a1 = hpack2n(p10, p11);
    f.a2 = hpack2n(p08, p09);
    f.a3 = hpack2n(p18, p19);
    return f;
}

__device__ __forceinline__ void attn_issue(uint32_t smb, int b, int h, int i0, int j0, int t) {
    const uint32_t bb = smb + (unsigned)b * BUFSZ;
#pragma unroll
    for (int q = 0; q < 4; q++) {
        int idx = t + q * 256;
        int j = idx >> 3, cc = idx & 7;
        unsigned so = (unsigned)j * 128u + (unsigned)((cc ^ (j & 7)) << 4);
        CPA16(bb + so, &g_Bf16[(size_t)(j0 + j) * OD + h * 64 + cc * 8]);
    }
    CPA16(bb + MSK_O + t * 16, &g_mask[(size_t)(i0 + t) * 128 + (j0 >> 5)]);
    if (t < 32) CPA16(bb + SSL_O + t * 16, &g_ssL[h * Nn + j0 + t * 4]);
}

__global__ void __launch_bounds__(256, 1) attn_mma_kernel() {
    extern __shared__ char dsm[];
    const uint32_t smb = smem_u32(dsm);

    const int h = blockIdx.x, it = blockIdx.y, i0 = it * 256;
    const int t = threadIdx.x, w = t >> 5, lane = t & 31;
    const int l3 = lane & 3, l7 = lane & 7, l15 = lane & 15;
    const int rB = w * 32 + (lane >> 2);
    const float sd0 = g_sdL[h * Nn + i0 + rB];
    const float sd1 = g_sdL[h * Nn + i0 + rB + 8];
    const float sd2 = g_sdL[h * Nn + i0 + rB + 16];
    const float sd3 = g_sdL[h * Nn + i0 + rB + 24];

    float z0 = 0.f, z1 = 0.f, z2 = 0.f, z3 = 0.f;
    float c[2][8][4];
#pragma unroll
    for (int blk = 0; blk < 2; blk++)
#pragma unroll
        for (int nt = 0; nt < 8; nt++)
#pragma unroll
            for (int q = 0; q < 4; q++) c[blk][nt][q] = 0.f;

    attn_issue(smb, 0, h, i0, 0, t);
    CPCOMMIT();

    for (int tl = 0; tl < NTILES; tl++) {
        if (tl < NTILES - 1) {
            attn_issue(smb, (tl + 1) & 1, h, i0, (tl + 1) * 128, t);
            CPCOMMIT();
            CPWAIT(1);
        } else {
            CPWAIT(0);
        }
        __syncthreads();

        const uint32_t bb = smb + (unsigned)(tl & 1) * BUFSZ;
        const char* bpd = dsm + (tl & 1) * BUFSZ;

#pragma unroll
        for (int kk = 0; kk < 8; kk++) {
            PFrag f0 = make_frag(bpd, kk, rB, rB + 8, sd0, sd1, l3, z0, z1);
            PFrag f1 = make_frag(bpd, kk, rB + 16, rB + 24, sd2, sd3, l3, z2, z3);

            const unsigned rowoff = (unsigned)(kk * 16 + l15) * 128u;
#pragma unroll
            for (int np = 0; np < 4; np++) {
                const unsigned chn =
                    (((unsigned)(np * 2 + (lane >> 4)) ^ (unsigned)l7) << 4);
                uint32_t bh0, bh1, bh2, bh3;
                LDMX4T(bh0, bh1, bh2, bh3, bb + rowoff + chn);
                MMA16(c[0][2 * np], f0.a0, f0.a1, f0.a2, f0.a3, bh0, bh1);
                MMA16(c[1][2 * np], f1.a0, f1.a1, f1.a2, f1.a3, bh0, bh1);
                MMA16(c[0][2 * np + 1], f0.a0, f0.a1, f0.a2, f0.a3, bh2, bh3);
                MMA16(c[1][2 * np + 1], f1.a0, f1.a1, f1.a2, f1.a3, bh2, bh3);
            }
        }
        __syncthreads();
    }

#pragma unroll
    for (int d = 1; d <= 2; d <<= 1) {
        z0 += __shfl_xor_sync(0xffffffffu, z0, d);
        z1 += __shfl_xor_sync(0xffffffffu, z1, d);
        z2 += __shfl_xor_sync(0xffffffffu, z2, d);
        z3 += __shfl_xor_sync(0xffffffffu, z3, d);
    }
    const float inv[4] = {1.0f / z0, 1.0f / z1, 1.0f / z2, 1.0f / z3};

    float* colS = (float*)(dsm + COLS_O);
    float* colQ = (float*)(dsm + COLQ_O);

#pragma unroll
    for (int nt = 0; nt < 8; nt++) {
        float vv[4][2];
#pragma unroll
        for (int blk = 0; blk < 2; blk++) {
#pragma unroll
            for (int half = 0; half < 2; half++) {
                const int ri = blk * 2 + half;
                float va = c[blk][nt][2 * half] * inv[ri];
                float vb = c[blk][nt][2 * half + 1] * inv[ri];
                vv[ri][0] = va;
                vv[ri][1] = vb;
                const int row = rB + blk * 16 + half * 8;
                *(float2*)&g_hp[(size_t)(i0 + row) * OD + h * 64 + nt * 8 + l3 * 2] =
                    make_float2(va, vb);
            }
        }
        float s0 = vv[0][0] + vv[1][0] + vv[2][0] + vv[3][0];
        float s1 = vv[0][1] + vv[1][1] + vv[2][1] + vv[3][1];
        float q0 = vv[0][0] * vv[0][0] + vv[1][0] * vv[1][0] + vv[2][0] * vv[2][0] +
                   vv[3][0] * vv[3][0];
        float q1 = vv[0][1] * vv[0][1] + vv[1][1] * vv[1][1] + vv[2][1] * vv[2][1] +
                   vv[3][1] * vv[3][1];
#pragma unroll
        for (int d = 4; d < 32; d <<= 1) {
            s0 += __shfl_xor_sync(0xffffffffu, s0, d);
            s1 += __shfl_xor_sync(0xffffffffu, s1, d);
            q0 += __shfl_xor_sync(0xffffffffu, q0, d);
            q1 += __shfl_xor_sync(0xffffffffu, q1, d);
        }
        if (lane < 4) {
            colS[w * 64 + nt * 8 + lane * 2] = s0;
            colS[w * 64 + nt * 8 + lane * 2 + 1] = s1;
            colQ[w * 64 + nt * 8 + lane * 2] = q0;
            colQ[w * 64 + nt * 8 + lane * 2 + 1] = q1;
        }
    }
    __syncthreads();
    if (t < 64) {
        float s = 0.f, q = 0.f;
#pragma unroll
        for (int ww = 0; ww < 8; ww++) {
            s += colS[ww * 64 + t];
            q += colQ[ww * 64 + t];
        }
        g_cs[it * OD + h * 64 + t] = s;
        g_cq[it * OD + h * 64 + t] = q;
    }
}

// ================= Kernel E: column stats =================
__global__ void __launch_bounds__(1024) colstats_kernel() {
    const int w = threadIdx.x >> 5, lane = threadIdx.x & 31;
    const int col = blockIdx.x * 32 + w;
    float s = (lane < ITILES) ? g_cs[lane * OD + col] : 0.f;
    float q = (lane < ITILES) ? g_cq[lane * OD + col] : 0.f;
#pragma unroll
    for (int d = 16; d >= 1; d >>= 1) {
        s += __shfl_xor_sync(0xffffffffu, s, d);
        q += __shfl_xor_sync(0xffffffffu, q, d);
    }
    if (lane == 0) {
        float mean = s * (1.0f / Nn);
        float var = q * (1.0f / Nn) - mean * mean;
        g_mean[col] = mean;
        g_rstd[col] = rsqrtf(var + EPSV);
    }
}

// ================= Kernel F: layernorm + relu =================
__global__ void __launch_bounds__(256) norm_relu_kernel(const float* __restrict__ gamma,
                                                        const float* __restrict__ beta,
                                                        float* __restrict__ out) {
    const int base8 = (blockIdx.x * 256 + threadIdx.x) * 8;
#pragma unroll
    for (int half = 0; half < 2; half++) {
        const int basei = base8 + half * 4;
        const int col = basei & (OD - 1);
        float4 xv = *(const float4*)&g_hp[basei];
        float4 mn = *(const float4*)&g_mean[col];
        float4 rs = *(const float4*)&g_rstd[col];
        float4 ga = *(const float4*)&gamma[col];
        float4 be = *(const float4*)&beta[col];
        float4 o;
        o.x = fmaxf(0.f, ga.x * (xv.x - mn.x) * rs.x + be.x);
        o.y = fmaxf(0.f, ga.y * (xv.y - mn.y) * rs.y + be.y);
        o.z = fmaxf(0.f, ga.z * (xv.z - mn.z) * rs.z + be.z);
        o.w = fmaxf(0.f, ga.w * (xv.w - mn.w) * rs.w + be.w);
        *(float4*)&out[basei] = o;
    }
}

// ================= launch =================
extern "C" void kernel_launch(void* const* d_in, const int* in_sizes, int n_in,
                              void* d_out, int out_size) {
    const float* x     = (const float*)d_in[0];
    const int*   adj   = (const int*)d_in[1];
    const float* W     = (const float*)d_in[2];
    const float* a     = (const float*)d_in[3];
    const float* gamma = (const float*)d_in[4];
    const float* beta  = (const float*)d_in[5];
    float* out = (float*)d_out;

    static int attrs_set = 0;
    if (!attrs_set) {
        cudaFuncSetAttribute(attn_mma_kernel,
                             cudaFuncAttributeMaxDynamicSharedMemorySize, SMEM_ATTN);
        cudaFuncSetAttribute(gemm_mma_kernel,
                             cudaFuncAttributeMaxDynamicSharedMemorySize, SMEM_GEMM);
        attrs_set = 1;
    }

    __nv_bfloat16 *xhi, *xlo, *whi, *wlo;
    cudaGetSymbolAddress((void**)&xhi, g_xhi);
    cudaGetSymbolAddress((void**)&xlo, g_xlo);
    cudaGetSymbolAddress((void**)&whi, g_whi);
    cudaGetSymbolAddress((void**)&wlo, g_wlo);

    cvt_kernel<<<(Nn * IND / 4) / 256, 256>>>(x, xhi, xlo);
    cvt_kernel<<<(OD * IND / 4) / 256, 256>>>(W, whi, wlo);
    gemm_mma_kernel<<<dim3(OD / 64, Nn / 128), 256, SMEM_GEMM>>>();
    scores_kernel<<<Nn / 8, 256>>>(a);
    maskpack_kernel<<<Nn, 256>>>(adj);
    attn_mma_kernel<<<dim3(Hh, ITILES), 256, SMEM_ATTN>>>();
    colstats_kernel<<<OD / 32, 1024>>>();
    norm_relu_kernel<<<(Nn * OD / 8) / 256, 256>>>(gamma, beta, out);
}